// round 1
// baseline (speedup 1.0000x reference)
#include <cuda_runtime.h>
#include <math.h>

#define N_  8
#define C_  64
#define H_  128
#define W_  256
#define HW_ (H_*W_)            // 32768
#define NELEM (N_*C_*H_*W_)    // 16777216

// Scratch (device globals — no allocation in kernel_launch)
__device__ float g_Ql[NELEM];
__device__ float g_Qr[NELEM];
__device__ float g_Vr[NELEM];
__device__ float g_t [NELEM];

// ---------------------------------------------------------------------------
// Kernel 1: t = x_r - avgpool3x3(x_r)   (count_include_pad -> always /9)
// ---------------------------------------------------------------------------
__global__ void __launch_bounds__(256) pre_kernel(const float* __restrict__ xr)
{
    const int tx = threadIdx.x, ty = threadIdx.y;
    const int w = blockIdx.x * 32 + tx;
    const int h = blockIdx.y * 8 + ty;
    const int plane = blockIdx.z;                 // n*64+c
    const float* p = xr + plane * HW_;
    float s = 0.f;
#pragma unroll
    for (int dy = -1; dy <= 1; dy++) {
        int hh = h + dy;
        if ((unsigned)hh < (unsigned)H_) {
#pragma unroll
            for (int dx = -1; dx <= 1; dx++) {
                int ww = w + dx;
                if ((unsigned)ww < (unsigned)W_) s += p[hh * W_ + ww];
            }
        }
    }
    g_t[plane * HW_ + h * W_ + w] = p[h * W_ + w] - s * (1.0f / 9.0f);
}

// ---------------------------------------------------------------------------
// Kernel 2: out = x_l + gamma * (conv3x3(t) + b_hf)
// block: 256 threads, 16x16 pixel tile, all 64 output channels in registers
// ---------------------------------------------------------------------------
__global__ void __launch_bounds__(256) conv_kernel(
    const float* __restrict__ xl, const float* __restrict__ gamma,
    const float* __restrict__ Whf, const float* __restrict__ bhf,
    float* __restrict__ out)
{
    __shared__ float s_t[18 * 19];   // input tile + halo, padded rows
    __shared__ float s_w[64 * 12];   // weights for 64 out-ch x 9 taps, row pad 12

    const int tid = threadIdx.x;
    const int w0 = blockIdx.x * 16, h0 = blockIdx.y * 16, n = blockIdx.z;
    const int px = tid & 15, py = tid >> 4;

    float acc[64];
#pragma unroll
    for (int o = 0; o < 64; o++) acc[o] = 0.f;

    for (int ci = 0; ci < 64; ci++) {
        const float* tp = g_t + (n * 64 + ci) * HW_;
        for (int i = tid; i < 324; i += 256) {
            int ty = i / 18, tx = i - ty * 18;
            int gh = h0 - 1 + ty, gw = w0 - 1 + tx;
            float v = 0.f;
            if ((unsigned)gh < (unsigned)H_ && (unsigned)gw < (unsigned)W_)
                v = tp[gh * W_ + gw];
            s_t[ty * 19 + tx] = v;
        }
        for (int i = tid; i < 576; i += 256) {
            int o = i / 9, tap = i - o * 9;
            s_w[o * 12 + tap] = Whf[(o * 64 + ci) * 9 + tap];
        }
        __syncthreads();

        float v[9];
#pragma unroll
        for (int ky = 0; ky < 3; ky++)
#pragma unroll
            for (int kx = 0; kx < 3; kx++)
                v[ky * 3 + kx] = s_t[(py + ky) * 19 + px + kx];

#pragma unroll
        for (int o = 0; o < 64; o++) {
            float4 a = *(const float4*)&s_w[o * 12];
            float4 b = *(const float4*)&s_w[o * 12 + 4];
            float c8 = s_w[o * 12 + 8];
            acc[o] += v[0]*a.x + v[1]*a.y + v[2]*a.z + v[3]*a.w
                    + v[4]*b.x + v[5]*b.y + v[6]*b.z + v[7]*b.w
                    + v[8]*c8;
        }
        __syncthreads();
    }

    const int h = h0 + py, w = w0 + px;
#pragma unroll
    for (int o = 0; o < 64; o++) {
        int idx = ((n * 64 + o) * H_ + h) * W_ + w;
        out[idx] = xl[idx] + gamma[o] * (acc[o] + bhf[o]);
    }
}

// ---------------------------------------------------------------------------
// Kernel 3: fused LayerNorm + 1x1 projections -> g_Ql, g_Qr, g_Vr (NHWC)
// block: 256 threads, tile = 64 pixels of one (n,h) row, all 64 channels
// ---------------------------------------------------------------------------
__device__ __forceinline__ void matvec_store(
    const float* __restrict__ sx,   // [c][w], stride 65
    const float* __restrict__ sw,   // [o][c], 64x64
    const float* __restrict__ sb,   // [o]
    float* __restrict__ gout,       // pixel-major NHWC chunk: gout[w*64+o]
    int tid)
{
    const int og = tid >> 6;    // 0..3
    const int w  = tid & 63;
    float acc[16];
#pragma unroll
    for (int oo = 0; oo < 16; oo++) acc[oo] = sb[og * 16 + oo];
#pragma unroll 4
    for (int c = 0; c < 64; c += 4) {
        float v0 = sx[(c    ) * 65 + w];
        float v1 = sx[(c + 1) * 65 + w];
        float v2 = sx[(c + 2) * 65 + w];
        float v3 = sx[(c + 3) * 65 + w];
#pragma unroll
        for (int oo = 0; oo < 16; oo++) {
            float4 wv = *(const float4*)&sw[(og * 16 + oo) * 64 + c];
            acc[oo] += v0 * wv.x + v1 * wv.y + v2 * wv.z + v3 * wv.w;
        }
    }
    float* gp = gout + w * 64 + og * 16;
#pragma unroll
    for (int oo = 0; oo < 16; oo += 4) {
        *(float4*)(gp + oo) = make_float4(acc[oo], acc[oo+1], acc[oo+2], acc[oo+3]);
    }
}

__global__ void __launch_bounds__(256) proj_kernel(
    const float* __restrict__ xl, const float* __restrict__ xr,
    const float* __restrict__ nlw, const float* __restrict__ nlb,
    const float* __restrict__ nrw, const float* __restrict__ nrb,
    const float* __restrict__ Wql, const float* __restrict__ bql,
    const float* __restrict__ Wqr, const float* __restrict__ bqr,
    const float* __restrict__ Wvr, const float* __restrict__ bvr)
{
    extern __shared__ float sm[];
    float* s_xl = sm;                // 64*65 = 4160
    float* s_xr = sm + 4160;         // 4160
    float* s_w  = sm + 8320;         // 4096
    float* s_mu = sm + 12416;        // 128 (l: 0..63, r: 64..127)
    float* s_rs = sm + 12544;        // 128
    float* s_b  = sm + 12672;        // 64      -> total 12736 floats

    const int tid = threadIdx.x;
    const int w0 = blockIdx.x * 64, h = blockIdx.y, n = blockIdx.z;
    const int base = (n * 64 * H_ + h) * W_ + w0;   // c=0 element

    // load x tiles: [c][w]
    for (int i = tid; i < 4096; i += 256) {
        int c = i >> 6, w = i & 63;
        s_xl[c * 65 + w] = xl[base + c * HW_ + w];
        s_xr[c * 65 + w] = xr[base + c * HW_ + w];
    }
    __syncthreads();

    // LN stats (128 threads: 64 for xl, 64 for xr) + load Wv in parallel
    if (tid < 128) {
        const float* sx = (tid < 64) ? s_xl : s_xr;
        int w = tid & 63;
        float s = 0.f, sq = 0.f;
#pragma unroll 8
        for (int c = 0; c < 64; c++) { float v = sx[c * 65 + w]; s += v; sq += v * v; }
        float mu  = s * (1.0f / 64.0f);
        float var = sq * (1.0f / 64.0f) - mu * mu;
        s_mu[tid] = mu;
        s_rs[tid] = rsqrtf(var + 1e-6f);
    }
    for (int i = tid; i < 4096; i += 256) s_w[i] = Wvr[i];
    if (tid < 64) s_b[tid] = bvr[tid];
    __syncthreads();

    // V_r from raw x_r
    matvec_store(s_xr, s_w, s_b, g_Vr + ((n * H_ + h) * W_ + w0) * 64, tid);
    __syncthreads();

    // normalize both tiles in place; load Wq_l
    for (int i = tid; i < 4096; i += 256) {
        int c = i >> 6, w = i & 63;
        s_xl[c * 65 + w] = (s_xl[c * 65 + w] - s_mu[w])      * s_rs[w]      * nlw[c] + nlb[c];
        s_xr[c * 65 + w] = (s_xr[c * 65 + w] - s_mu[64 + w]) * s_rs[64 + w] * nrw[c] + nrb[c];
    }
    for (int i = tid; i < 4096; i += 256) s_w[i] = Wql[i];
    if (tid < 64) s_b[tid] = bql[tid];
    __syncthreads();

    matvec_store(s_xl, s_w, s_b, g_Ql + ((n * H_ + h) * W_ + w0) * 64, tid);
    __syncthreads();

    for (int i = tid; i < 4096; i += 256) s_w[i] = Wqr[i];
    if (tid < 64) s_b[tid] = bqr[tid];
    __syncthreads();

    matvec_store(s_xr, s_w, s_b, g_Qr + ((n * H_ + h) * W_ + w0) * 64, tid);
}

// ---------------------------------------------------------------------------
// Kernel 4: per-scanline cross attention. Block per (n,h). 256 threads.
// out[idx] += beta[c] * (softmax(Ql·Qr^T/8) @ Vr)
// ---------------------------------------------------------------------------
__global__ void __launch_bounds__(256) attn_kernel(
    const float* __restrict__ beta, float* __restrict__ out)
{
    extern __shared__ float sm[];
    float* s_Qr = sm;                // 256*64 = 16384
    float* s_Vr = sm + 16384;        // 16384
    float* s_Ql = sm + 32768;        // 64*65  = 4160
    float* s_P  = sm + 36928;        // 64*257 = 16448
    float* s_rm = sm + 53376;        // 256
    float* s_rsm= sm + 53632;        // 256   -> total 53888 floats

    const int tid = threadIdx.x;
    const int h = blockIdx.x, n = blockIdx.y;
    const int sbase = (n * H_ + h) * W_ * 64;

    for (int i = tid; i < 16384; i += 256) {
        s_Qr[i] = g_Qr[sbase + i];
        s_Vr[i] = g_Vr[sbase + i];
    }

    const int j = tid >> 6, q = tid & 63;       // score phase: warp-uniform j
    const int warp = tid >> 5, lane = tid & 31; // PV phase
    const int c0 = warp * 8;
    float bet[8];
#pragma unroll
    for (int cc = 0; cc < 8; cc++) bet[cc] = beta[c0 + cc];

    for (int qt = 0; qt < 4; qt++) {
        __syncthreads();   // tiles ready (iter 0) / previous PV finished

        for (int i = tid; i < 4096; i += 256) {
            int qq = i >> 6, c = i & 63;
            s_Ql[qq * 65 + c] = g_Ql[sbase + (qt * 64 + qq) * 64 + c];
        }
        __syncthreads();

        // scores: this thread -> query q, keys [j*64, j*64+64)
        float sc[64];
        const float* qlrow = &s_Ql[q * 65];
#pragma unroll
        for (int k0 = 0; k0 < 64; k0 += 8) {
            float a0=0.f,a1=0.f,a2=0.f,a3=0.f,a4=0.f,a5=0.f,a6=0.f,a7=0.f;
            const float* qr = &s_Qr[(j * 64 + k0) * 64];
#pragma unroll 4
            for (int c = 0; c < 64; c += 4) {
                float q0 = qlrow[c], q1 = qlrow[c+1], q2 = qlrow[c+2], q3 = qlrow[c+3];
                float4 v;
                v = *(const float4*)&qr[0*64 + c]; a0 += q0*v.x + q1*v.y + q2*v.z + q3*v.w;
                v = *(const float4*)&qr[1*64 + c]; a1 += q0*v.x + q1*v.y + q2*v.z + q3*v.w;
                v = *(const float4*)&qr[2*64 + c]; a2 += q0*v.x + q1*v.y + q2*v.z + q3*v.w;
                v = *(const float4*)&qr[3*64 + c]; a3 += q0*v.x + q1*v.y + q2*v.z + q3*v.w;
                v = *(const float4*)&qr[4*64 + c]; a4 += q0*v.x + q1*v.y + q2*v.z + q3*v.w;
                v = *(const float4*)&qr[5*64 + c]; a5 += q0*v.x + q1*v.y + q2*v.z + q3*v.w;
                v = *(const float4*)&qr[6*64 + c]; a6 += q0*v.x + q1*v.y + q2*v.z + q3*v.w;
                v = *(const float4*)&qr[7*64 + c]; a7 += q0*v.x + q1*v.y + q2*v.z + q3*v.w;
            }
            sc[k0+0] = a0 * 0.125f; sc[k0+1] = a1 * 0.125f;
            sc[k0+2] = a2 * 0.125f; sc[k0+3] = a3 * 0.125f;
            sc[k0+4] = a4 * 0.125f; sc[k0+5] = a5 * 0.125f;
            sc[k0+6] = a6 * 0.125f; sc[k0+7] = a7 * 0.125f;
        }

        // softmax over all 256 keys (partials across the 4 j-groups)
        float m = sc[0];
#pragma unroll
        for (int k = 1; k < 64; k++) m = fmaxf(m, sc[k]);
        s_rm[j * 64 + q] = m;
        __syncthreads();
        m = fmaxf(fmaxf(s_rm[q], s_rm[64 + q]), fmaxf(s_rm[128 + q], s_rm[192 + q]));
        float ssum = 0.f;
#pragma unroll
        for (int k = 0; k < 64; k++) { float e = __expf(sc[k] - m); sc[k] = e; ssum += e; }
        s_rsm[j * 64 + q] = ssum;
        __syncthreads();
        float tot = s_rsm[q] + s_rsm[64 + q] + s_rsm[128 + q] + s_rsm[192 + q];
        float inv = __fdividef(1.0f, tot);
#pragma unroll
        for (int k = 0; k < 64; k++) s_P[q * 257 + j * 64 + k] = sc[k] * inv;
        __syncthreads();

        // PV: warp handles 8 channels, thread handles queries {lane, lane+32}
        float acc[2][8];
#pragma unroll
        for (int i2 = 0; i2 < 2; i2++)
#pragma unroll
            for (int cc = 0; cc < 8; cc++) acc[i2][cc] = 0.f;

#pragma unroll 4
        for (int k = 0; k < 256; k++) {
            float p0 = s_P[lane * 257 + k];
            float p1 = s_P[(lane + 32) * 257 + k];
            float4 va = *(const float4*)&s_Vr[k * 64 + c0];
            float4 vb = *(const float4*)&s_Vr[k * 64 + c0 + 4];
            acc[0][0] += p0 * va.x; acc[0][1] += p0 * va.y;
            acc[0][2] += p0 * va.z; acc[0][3] += p0 * va.w;
            acc[0][4] += p0 * vb.x; acc[0][5] += p0 * vb.y;
            acc[0][6] += p0 * vb.z; acc[0][7] += p0 * vb.w;
            acc[1][0] += p1 * va.x; acc[1][1] += p1 * va.y;
            acc[1][2] += p1 * va.z; acc[1][3] += p1 * va.w;
            acc[1][4] += p1 * vb.x; acc[1][5] += p1 * vb.y;
            acc[1][6] += p1 * vb.z; acc[1][7] += p1 * vb.w;
        }

        const int wq0 = qt * 64;
#pragma unroll
        for (int i2 = 0; i2 < 2; i2++) {
            int wq = wq0 + lane + i2 * 32;
#pragma unroll
            for (int cc = 0; cc < 8; cc++) {
                int idx = ((n * 64 + c0 + cc) * H_ + h) * W_ + wq;
                out[idx] += bet[cc] * acc[i2][cc];
            }
        }
    }
}

// ---------------------------------------------------------------------------
extern "C" void kernel_launch(void* const* d_in, const int* in_sizes, int n_in,
                              void* d_out, int out_size)
{
    const float* x_l  = (const float*)d_in[0];
    const float* x_r  = (const float*)d_in[1];
    const float* nl_w = (const float*)d_in[2];
    const float* nl_b = (const float*)d_in[3];
    const float* nr_w = (const float*)d_in[4];
    const float* nr_b = (const float*)d_in[5];
    const float* Wq_l = (const float*)d_in[6];
    const float* bq_l = (const float*)d_in[7];
    const float* Wq_r = (const float*)d_in[8];
    const float* bq_r = (const float*)d_in[9];
    const float* Wv_r = (const float*)d_in[10];
    const float* bv_r = (const float*)d_in[11];
    const float* beta = (const float*)d_in[12];
    const float* gamma= (const float*)d_in[13];
    const float* W_hf = (const float*)d_in[14];
    const float* b_hf = (const float*)d_in[15];
    float* out = (float*)d_out;

    cudaFuncSetAttribute(proj_kernel, cudaFuncAttributeMaxDynamicSharedMemorySize, 12736 * 4);
    cudaFuncSetAttribute(attn_kernel, cudaFuncAttributeMaxDynamicSharedMemorySize, 53888 * 4);

    pre_kernel <<<dim3(W_/32, H_/8, N_*C_), dim3(32, 8)>>>(x_r);
    conv_kernel<<<dim3(W_/16, H_/16, N_), 256>>>(x_l, gamma, W_hf, b_hf, out);
    proj_kernel<<<dim3(W_/64, H_, N_), 256, 12736 * 4>>>(
        x_l, x_r, nl_w, nl_b, nr_w, nr_b, Wq_l, bq_l, Wq_r, bq_r, Wv_r, bv_r);
    attn_kernel<<<dim3(H_, N_), 256, 53888 * 4>>>(beta, out);
}

// round 4
// speedup vs baseline: 1.4264x; 1.4264x over previous
#include <cuda_runtime.h>
#include <cuda_fp16.h>
#include <math.h>
#include <stdint.h>

#define N_  8
#define C_  64
#define H_  128
#define W_  256
#define HW_ (H_*W_)            // 32768
#define NELEM (N_*C_*H_*W_)    // 16777216

// Scratch (device globals — no allocation in kernel_launch)
__device__ float  g_t  [NELEM];   // hf-branch input
__device__ __half g_Qlh[NELEM];   // [n,h,q,c]  pixel-major, 64 half = 128B rows
__device__ __half g_Qrh[NELEM];   // [n,h,k,c]
__device__ __half g_Vth[NELEM];   // [n,h,c,k]  transposed: 64 rows of 256 halves

// ===========================================================================
__device__ __forceinline__ uint32_t smem_u32(const void* p) {
    uint32_t a;
    asm("{ .reg .u64 t; cvta.to.shared.u64 t, %1; cvt.u32.u64 %0, t; }"
        : "=r"(a) : "l"(p));
    return a;
}
__device__ __forceinline__ void ldsm_x4(uint32_t* r, uint32_t addr) {
    asm volatile("ldmatrix.sync.aligned.m8n8.x4.shared.b16 {%0,%1,%2,%3}, [%4];"
                 : "=r"(r[0]), "=r"(r[1]), "=r"(r[2]), "=r"(r[3]) : "r"(addr));
}
__device__ __forceinline__ void mma16816(float* d, const uint32_t* a,
                                         const uint32_t b0, const uint32_t b1) {
    asm volatile(
        "mma.sync.aligned.m16n8k16.row.col.f32.f16.f16.f32 "
        "{%0,%1,%2,%3}, {%4,%5,%6,%7}, {%8,%9}, {%0,%1,%2,%3};"
        : "+f"(d[0]), "+f"(d[1]), "+f"(d[2]), "+f"(d[3])
        : "r"(a[0]), "r"(a[1]), "r"(a[2]), "r"(a[3]), "r"(b0), "r"(b1));
}

// ---------------------------------------------------------------------------
// Kernel 1: t = x_r - avgpool3x3(x_r)
// ---------------------------------------------------------------------------
__global__ void __launch_bounds__(256) pre_kernel(const float* __restrict__ xr)
{
    const int tx = threadIdx.x, ty = threadIdx.y;
    const int w = blockIdx.x * 32 + tx;
    const int h = blockIdx.y * 8 + ty;
    const int plane = blockIdx.z;
    const float* p = xr + plane * HW_;
    float s = 0.f;
#pragma unroll
    for (int dy = -1; dy <= 1; dy++) {
        int hh = h + dy;
        if ((unsigned)hh < (unsigned)H_) {
#pragma unroll
            for (int dx = -1; dx <= 1; dx++) {
                int ww = w + dx;
                if ((unsigned)ww < (unsigned)W_) s += p[hh * W_ + ww];
            }
        }
    }
    g_t[plane * HW_ + h * W_ + w] = p[h * W_ + w] - s * (1.0f / 9.0f);
}

// ---------------------------------------------------------------------------
// Kernel 2: out = x_l + gamma * (conv3x3(t) + b_hf)
// ---------------------------------------------------------------------------
__global__ void __launch_bounds__(256) conv_kernel(
    const float* __restrict__ xl, const float* __restrict__ gamma,
    const float* __restrict__ Whf, const float* __restrict__ bhf,
    float* __restrict__ out)
{
    __shared__ float s_t[18 * 19];
    __shared__ float s_w[64 * 12];

    const int tid = threadIdx.x;
    const int w0 = blockIdx.x * 16, h0 = blockIdx.y * 16, n = blockIdx.z;
    const int px = tid & 15, py = tid >> 4;

    float acc[64];
#pragma unroll
    for (int o = 0; o < 64; o++) acc[o] = 0.f;

    for (int ci = 0; ci < 64; ci++) {
        const float* tp = g_t + (n * 64 + ci) * HW_;
        for (int i = tid; i < 324; i += 256) {
            int ty = i / 18, tx = i - ty * 18;
            int gh = h0 - 1 + ty, gw = w0 - 1 + tx;
            float v = 0.f;
            if ((unsigned)gh < (unsigned)H_ && (unsigned)gw < (unsigned)W_)
                v = tp[gh * W_ + gw];
            s_t[ty * 19 + tx] = v;
        }
        for (int i = tid; i < 576; i += 256) {
            int o = i / 9, tap = i - o * 9;
            s_w[o * 12 + tap] = Whf[(o * 64 + ci) * 9 + tap];
        }
        __syncthreads();

        float v[9];
#pragma unroll
        for (int ky = 0; ky < 3; ky++)
#pragma unroll
            for (int kx = 0; kx < 3; kx++)
                v[ky * 3 + kx] = s_t[(py + ky) * 19 + px + kx];

#pragma unroll
        for (int o = 0; o < 64; o++) {
            float4 a = *(const float4*)&s_w[o * 12];
            float4 b = *(const float4*)&s_w[o * 12 + 4];
            float c8 = s_w[o * 12 + 8];
            acc[o] += v[0]*a.x + v[1]*a.y + v[2]*a.z + v[3]*a.w
                    + v[4]*b.x + v[5]*b.y + v[6]*b.z + v[7]*b.w
                    + v[8]*c8;
        }
        __syncthreads();
    }

    const int h = h0 + py, w = w0 + px;
#pragma unroll
    for (int o = 0; o < 64; o++) {
        int idx = ((n * 64 + o) * H_ + h) * W_ + w;
        out[idx] = xl[idx] + gamma[o] * (acc[o] + bhf[o]);
    }
}

// ---------------------------------------------------------------------------
// Kernel 3: fused LayerNorm + 1x1 projections -> fp16 Q_l, Q_r, V^T
// ---------------------------------------------------------------------------
__device__ __forceinline__ void matvec16(
    const float* __restrict__ sx,   // [c][w], stride 65
    const float* __restrict__ sw,   // [o][c]
    const float* __restrict__ sb,   // [o]
    float* __restrict__ acc, int tid)
{
    const int og = tid >> 6;
    const int w  = tid & 63;
#pragma unroll
    for (int oo = 0; oo < 16; oo++) acc[oo] = sb[og * 16 + oo];
#pragma unroll 4
    for (int c = 0; c < 64; c += 4) {
        float v0 = sx[(c    ) * 65 + w];
        float v1 = sx[(c + 1) * 65 + w];
        float v2 = sx[(c + 2) * 65 + w];
        float v3 = sx[(c + 3) * 65 + w];
#pragma unroll
        for (int oo = 0; oo < 16; oo++) {
            float4 wv = *(const float4*)&sw[(og * 16 + oo) * 64 + c];
            acc[oo] += v0 * wv.x + v1 * wv.y + v2 * wv.z + v3 * wv.w;
        }
    }
}

__device__ __forceinline__ void store_q_half(float* acc, __half* gq, int tid, int w0)
{
    const int og = tid >> 6, w = tid & 63;
    __half2 h2[8];
#pragma unroll
    for (int oo = 0; oo < 8; oo++)
        h2[oo] = __floats2half2_rn(acc[2*oo], acc[2*oo+1]);
    uint4* dst = (uint4*)(gq + (size_t)(w0 + w) * 64 + og * 16);
    dst[0] = ((uint4*)h2)[0];
    dst[1] = ((uint4*)h2)[1];
}

__global__ void __launch_bounds__(256) proj_kernel(
    const float* __restrict__ xl, const float* __restrict__ xr,
    const float* __restrict__ nlw, const float* __restrict__ nlb,
    const float* __restrict__ nrw, const float* __restrict__ nrb,
    const float* __restrict__ Wql, const float* __restrict__ bql,
    const float* __restrict__ Wqr, const float* __restrict__ bqr,
    const float* __restrict__ Wvr, const float* __restrict__ bvr)
{
    extern __shared__ float sm[];
    float* s_xl = sm;                // 4160
    float* s_xr = sm + 4160;         // 4160
    float* s_w  = sm + 8320;         // 4096
    float* s_mu = sm + 12416;        // 128
    float* s_rs = sm + 12544;        // 128
    float* s_b  = sm + 12672;        // 64

    const int tid = threadIdx.x;
    const int w0 = blockIdx.x * 64, h = blockIdx.y, n = blockIdx.z;
    const int base = (n * 64 * H_ + h) * W_ + w0;
    const size_t pbase = (size_t)(n * H_ + h) * W_ * 64;   // halves

    for (int i = tid; i < 4096; i += 256) {
        int c = i >> 6, w = i & 63;
        s_xl[c * 65 + w] = xl[base + c * HW_ + w];
        s_xr[c * 65 + w] = xr[base + c * HW_ + w];
    }
    __syncthreads();

    if (tid < 128) {
        const float* sx = (tid < 64) ? s_xl : s_xr;
        int w = tid & 63;
        float s = 0.f, sq = 0.f;
#pragma unroll 8
        for (int c = 0; c < 64; c++) { float v = sx[c * 65 + w]; s += v; sq += v * v; }
        float mu  = s * (1.0f / 64.0f);
        float var = sq * (1.0f / 64.0f) - mu * mu;
        s_mu[tid] = mu;
        s_rs[tid] = rsqrtf(var + 1e-6f);
    }
    for (int i = tid; i < 4096; i += 256) s_w[i] = Wvr[i];
    if (tid < 64) s_b[tid] = bvr[tid];
    __syncthreads();

    // V_r from raw x_r -> transposed fp16 [c][k]
    {
        float acc[16];
        matvec16(s_xr, s_w, s_b, acc, tid);
        const int og = tid >> 6, w = tid & 63;
        __half* vp = g_Vth + pbase;
#pragma unroll
        for (int oo = 0; oo < 16; oo++)
            vp[(size_t)(og * 16 + oo) * 256 + w0 + w] = __float2half(acc[oo]);
    }
    __syncthreads();

    for (int i = tid; i < 4096; i += 256) {
        int c = i >> 6, w = i & 63;
        s_xl[c * 65 + w] = (s_xl[c * 65 + w] - s_mu[w])      * s_rs[w]      * nlw[c] + nlb[c];
        s_xr[c * 65 + w] = (s_xr[c * 65 + w] - s_mu[64 + w]) * s_rs[64 + w] * nrw[c] + nrb[c];
    }
    for (int i = tid; i < 4096; i += 256) s_w[i] = Wql[i];
    if (tid < 64) s_b[tid] = bql[tid];
    __syncthreads();

    {
        float acc[16];
        matvec16(s_xl, s_w, s_b, acc, tid);
        store_q_half(acc, g_Qlh + pbase, tid, w0);
    }
    __syncthreads();

    for (int i = tid; i < 4096; i += 256) s_w[i] = Wqr[i];
    if (tid < 64) s_b[tid] = bqr[tid];
    __syncthreads();

    {
        float acc[16];
        matvec16(s_xr, s_w, s_b, acc, tid);
        store_q_half(acc, g_Qrh + pbase, tid, w0);
    }
}

// ---------------------------------------------------------------------------
// Kernel 4: warp-MMA fp16 cross attention (mma.sync m16n8k16, HMMA path).
// Block per (n,h), 8 warps. Warp handles two 16-query tiles, online softmax
// over 16-key chunks, full 256-key rows.
// ---------------------------------------------------------------------------
#define QL_STRIDE 72      // halves: 144B, 16B-aligned, conflict-free mod 128
#define VT_STRIDE 264     // halves: 528B
#define P_STRIDE  24      // halves: 48B
#define SM_QL 0
#define SM_QR (SM_QL + 256 * QL_STRIDE * 2)          // 36864
#define SM_VT (SM_QR + 256 * QL_STRIDE * 2)          // 73728
#define SM_P  (SM_VT + 64 * VT_STRIDE * 2)           // 107520
#define AT_SMEM (SM_P + 8 * 16 * P_STRIDE * 2)       // 113664

__global__ void __launch_bounds__(256, 2) attn_kernel(
    const float* __restrict__ beta, float* __restrict__ out)
{
    extern __shared__ __align__(16) char smem[];
    __half* s_ql = (__half*)(smem + SM_QL);
    __half* s_qr = (__half*)(smem + SM_QR);
    __half* s_vt = (__half*)(smem + SM_VT);

    const int tid = threadIdx.x, wid = tid >> 5, lane = tid & 31;
    const int h = blockIdx.x, n = blockIdx.y;
    const size_t pbase = (size_t)(n * H_ + h) * W_ * 64;   // halves

    // ---- load tiles (gmem rows are 16B-aligned) ----
    {
        const uint4* gql = (const uint4*)(g_Qlh + pbase);
        const uint4* gqr = (const uint4*)(g_Qrh + pbase);
        const uint4* gvt = (const uint4*)(g_Vth + pbase);
        for (int i = tid; i < 2048; i += 256) {            // 256 rows x 4 seg
            int row = i >> 3, seg = i & 7;
            ((uint4*)(s_ql + row * QL_STRIDE))[seg] = gql[i];
            ((uint4*)(s_qr + row * QL_STRIDE))[seg] = gqr[i];
        }
        for (int i = tid; i < 2048; i += 256) {            // 64 rows x 16 seg
            int row = i >> 5, seg = i & 31;
            ((uint4*)(s_vt + row * VT_STRIDE))[seg] = gvt[i];
        }
    }
    __syncthreads();

    const uint32_t ql_b = smem_u32(s_ql);
    const uint32_t qr_b = smem_u32(s_qr);
    const uint32_t vt_b = smem_u32(s_vt);
    const uint32_t p_b  = smem_u32(smem + SM_P) + wid * (16 * P_STRIDE * 2);

    const int r  = lane >> 2;       // 0..7
    const int tc = lane & 3;

    // lane-dependent ldmatrix source addresses (byte offsets)
    // A-style (16 rows x 2 col-halves): row = lane&15, colhalf = lane>>4
    const int a_row = lane & 15, a_ch = lane >> 4;
    // B-style: row = (lane&7) + (lane>>4)*8, colhalf = (lane>>3)&1
    const int b_row = (lane & 7) + ((lane >> 4) << 3);
    const int b_ch  = (lane >> 3) & 1;

    const uint32_t p_addr = p_b + a_row * (P_STRIDE * 2) + a_ch * 16;

#pragma unroll 1
    for (int qt = 0; qt < 2; qt++) {
        const int qbase = (wid * 2 + qt) * 16;

        // A fragments of Ql for k = 0..63 (4 ksteps)
        uint32_t aQ[4][4];
#pragma unroll
        for (int ks = 0; ks < 4; ks++) {
            uint32_t addr = ql_b + (qbase + a_row) * (QL_STRIDE * 2)
                          + (ks * 16 + a_ch * 8) * 2;
            ldsm_x4(aQ[ks], addr);
        }

        float o[8][4];
#pragma unroll
        for (int nc = 0; nc < 8; nc++)
#pragma unroll
            for (int j = 0; j < 4; j++) o[nc][j] = 0.f;
        float m_r = -1e30f, m_r8 = -1e30f;
        float l_r = 0.f,    l_r8 = 0.f;

#pragma unroll 1
        for (int kk = 0; kk < 16; kk++) {
            const int kbase = kk * 16;

            // ---- S chunk: 16 q x 16 keys ----
            float s0[4] = {0.f, 0.f, 0.f, 0.f};   // keys kbase+0..7
            float s1[4] = {0.f, 0.f, 0.f, 0.f};   // keys kbase+8..15
#pragma unroll
            for (int ks = 0; ks < 4; ks++) {
                uint32_t br[4];
                uint32_t addr = qr_b + (kbase + b_row) * (QL_STRIDE * 2)
                              + (ks * 16 + b_ch * 8) * 2;
                ldsm_x4(br, addr);
                mma16816(s0, aQ[ks], br[0], br[1]);
                mma16816(s1, aQ[ks], br[2], br[3]);
            }

            // ---- online softmax (scale 1/8) ----
            float cm_r  = fmaxf(fmaxf(s0[0], s0[1]), fmaxf(s1[0], s1[1]));
            float cm_r8 = fmaxf(fmaxf(s0[2], s0[3]), fmaxf(s1[2], s1[3]));
            cm_r  = fmaxf(cm_r,  __shfl_xor_sync(0xffffffff, cm_r,  1));
            cm_r  = fmaxf(cm_r,  __shfl_xor_sync(0xffffffff, cm_r,  2));
            cm_r8 = fmaxf(cm_r8, __shfl_xor_sync(0xffffffff, cm_r8, 1));
            cm_r8 = fmaxf(cm_r8, __shfl_xor_sync(0xffffffff, cm_r8, 2));
            float mn_r  = fmaxf(m_r,  cm_r  * 0.125f);
            float mn_r8 = fmaxf(m_r8, cm_r8 * 0.125f);
            float al_r  = __expf(m_r  - mn_r);
            float al_r8 = __expf(m_r8 - mn_r8);
            m_r = mn_r; m_r8 = mn_r8;

            float p00 = __expf(fmaf(s0[0], 0.125f, -mn_r));
            float p01 = __expf(fmaf(s0[1], 0.125f, -mn_r));
            float p10 = __expf(fmaf(s1[0], 0.125f, -mn_r));
            float p11 = __expf(fmaf(s1[1], 0.125f, -mn_r));
            float q00 = __expf(fmaf(s0[2], 0.125f, -mn_r8));
            float q01 = __expf(fmaf(s0[3], 0.125f, -mn_r8));
            float q10 = __expf(fmaf(s1[2], 0.125f, -mn_r8));
            float q11 = __expf(fmaf(s1[3], 0.125f, -mn_r8));
            l_r  = l_r  * al_r  + (p00 + p01) + (p10 + p11);
            l_r8 = l_r8 * al_r8 + (q00 + q01) + (q10 + q11);

#pragma unroll
            for (int nc = 0; nc < 8; nc++) {
                o[nc][0] *= al_r;  o[nc][1] *= al_r;
                o[nc][2] *= al_r8; o[nc][3] *= al_r8;
            }

            // ---- P chunk to smem (protect previous ldmatrix reads) ----
            __syncwarp();
            {
                __half* pw = (__half*)(smem + SM_P) + wid * (16 * P_STRIDE);
                *(__half2*)&pw[r * P_STRIDE + 2 * tc]           = __floats2half2_rn(p00, p01);
                *(__half2*)&pw[r * P_STRIDE + 8 + 2 * tc]       = __floats2half2_rn(p10, p11);
                *(__half2*)&pw[(r + 8) * P_STRIDE + 2 * tc]     = __floats2half2_rn(q00, q01);
                *(__half2*)&pw[(r + 8) * P_STRIDE + 8 + 2 * tc] = __floats2half2_rn(q10, q11);
            }
            __syncwarp();

            uint32_t aP[4];
            ldsm_x4(aP, p_addr);

            // ---- PV: 8 c-ntiles ----
#pragma unroll
            for (int vg = 0; vg < 4; vg++) {
                uint32_t bv[4];
                uint32_t addr = vt_b + (vg * 16 + b_row) * (VT_STRIDE * 2)
                              + (kbase + b_ch * 8) * 2;
                ldsm_x4(bv, addr);
                mma16816(o[2 * vg],     aP, bv[0], bv[1]);
                mma16816(o[2 * vg + 1], aP, bv[2], bv[3]);
            }
        }

        // ---- finalize: l reduce + normalize + epilogue ----
        l_r  += __shfl_xor_sync(0xffffffff, l_r,  1);
        l_r  += __shfl_xor_sync(0xffffffff, l_r,  2);
        l_r8 += __shfl_xor_sync(0xffffffff, l_r8, 1);
        l_r8 += __shfl_xor_sync(0xffffffff, l_r8, 2);
        float inv_r  = __fdividef(1.f, l_r);
        float inv_r8 = __fdividef(1.f, l_r8);

#pragma unroll
        for (int nc = 0; nc < 8; nc++) {
            int c0 = nc * 8 + 2 * tc;
            float b0 = beta[c0], b1 = beta[c0 + 1];
            size_t base0 = (((size_t)n * 64 + c0) * H_ + h) * W_ + qbase;
            out[base0 + r]            += b0 * o[nc][0] * inv_r;
            out[base0 + HW_ + r]      += b1 * o[nc][1] * inv_r;
            out[base0 + r + 8]        += b0 * o[nc][2] * inv_r8;
            out[base0 + HW_ + r + 8]  += b1 * o[nc][3] * inv_r8;
        }
    }
}

// ---------------------------------------------------------------------------
extern "C" void kernel_launch(void* const* d_in, const int* in_sizes, int n_in,
                              void* d_out, int out_size)
{
    const float* x_l  = (const float*)d_in[0];
    const float* x_r  = (const float*)d_in[1];
    const float* nl_w = (const float*)d_in[2];
    const float* nl_b = (const float*)d_in[3];
    const float* nr_w = (const float*)d_in[4];
    const float* nr_b = (const float*)d_in[5];
    const float* Wq_l = (const float*)d_in[6];
    const float* bq_l = (const float*)d_in[7];
    const float* Wq_r = (const float*)d_in[8];
    const float* bq_r = (const float*)d_in[9];
    const float* Wv_r = (const float*)d_in[10];
    const float* bv_r = (const float*)d_in[11];
    const float* beta = (const float*)d_in[12];
    const float* gamma= (const float*)d_in[13];
    const float* W_hf = (const float*)d_in[14];
    const float* b_hf = (const float*)d_in[15];
    float* out = (float*)d_out;

    cudaFuncSetAttribute(proj_kernel, cudaFuncAttributeMaxDynamicSharedMemorySize, 12736 * 4);
    cudaFuncSetAttribute(attn_kernel, cudaFuncAttributeMaxDynamicSharedMemorySize, AT_SMEM);

    pre_kernel <<<dim3(W_/32, H_/8, N_*C_), dim3(32, 8)>>>(x_r);
    conv_kernel<<<dim3(W_/16, H_/16, N_), 256>>>(x_l, gamma, W_hf, b_hf, out);
    proj_kernel<<<dim3(W_/64, H_, N_), 256, 12736 * 4>>>(
        x_l, x_r, nl_w, nl_b, nr_w, nr_b, Wq_l, bq_l, Wq_r, bq_r, Wv_r, bv_r);
    attn_kernel<<<dim3(H_, N_), 256, AT_SMEM>>>(beta, out);
}

// round 5
// speedup vs baseline: 3.0677x; 2.1507x over previous
#include <cuda_runtime.h>
#include <cuda_fp16.h>
#include <math.h>
#include <stdint.h>

#define N_  8
#define C_  64
#define H_  128
#define W_  256
#define HW_ (H_*W_)            // 32768
#define NELEM (N_*C_*H_*W_)    // 16777216

// Scratch (device globals — no allocation in kernel_launch)
__device__ __half g_th [NELEM];   // hf input, pixel-major [n][h][w][c] fp16
__device__ __half g_W9h[9*64*64]; // conv weights [tap][o][c] fp16
__device__ __half g_Qlh[NELEM];   // [n,h,q,c]
__device__ __half g_Qrh[NELEM];   // [n,h,k,c]
__device__ __half g_Vth[NELEM];   // [n,h,c,k]

// ===========================================================================
__device__ __forceinline__ uint32_t smem_u32(const void* p) {
    uint32_t a;
    asm("{ .reg .u64 t; cvta.to.shared.u64 t, %1; cvt.u32.u64 %0, t; }"
        : "=r"(a) : "l"(p));
    return a;
}
__device__ __forceinline__ void ldsm_x4(uint32_t* r, uint32_t addr) {
    asm volatile("ldmatrix.sync.aligned.m8n8.x4.shared.b16 {%0,%1,%2,%3}, [%4];"
                 : "=r"(r[0]), "=r"(r[1]), "=r"(r[2]), "=r"(r[3]) : "r"(addr));
}
__device__ __forceinline__ void mma16816(float* d, const uint32_t* a,
                                         const uint32_t b0, const uint32_t b1) {
    asm volatile(
        "mma.sync.aligned.m16n8k16.row.col.f32.f16.f16.f32 "
        "{%0,%1,%2,%3}, {%4,%5,%6,%7}, {%8,%9}, {%0,%1,%2,%3};"
        : "+f"(d[0]), "+f"(d[1]), "+f"(d[2]), "+f"(d[3])
        : "r"(a[0]), "r"(a[1]), "r"(a[2]), "r"(a[3]), "r"(b0), "r"(b1));
}

// ---------------------------------------------------------------------------
// Kernel 0: W_hf (O,I,3,3) fp32 -> g_W9h [tap][o][c] fp16
// ---------------------------------------------------------------------------
__global__ void __launch_bounds__(256) wconv_kernel(const float* __restrict__ Whf)
{
    int i = blockIdx.x * 256 + threadIdx.x;          // 36864 total
    if (i < 9 * 64 * 64) {
        int tap = i >> 12, rem = i & 4095;
        int o = rem >> 6, c = rem & 63;
        g_W9h[i] = __float2half(Whf[(o * 64 + c) * 9 + tap]);
    }
}

// ---------------------------------------------------------------------------
// Kernel 1: t = x_r - avgpool3x3(x_r), fp16 pixel-major out
// grid (W/64, H, N), 256 threads: 4 channels x 64 pixels per iter
// ---------------------------------------------------------------------------
#define PB_STRIDE 72
__global__ void __launch_bounds__(256) pre_kernel(const float* __restrict__ xr)
{
    __shared__ __half s_buf[64 * PB_STRIDE];

    const int tid = threadIdx.x;
    const int w0 = blockIdx.x * 64, h = blockIdx.y, n = blockIdx.z;
    const int cg = tid >> 6, w = tid & 63;
    const int gw = w0 + w;

#pragma unroll 1
    for (int c0 = 0; c0 < 64; c0 += 4) {
        int c = c0 + cg;
        const float* p = xr + (size_t)(n * 64 + c) * HW_;
        float s = 0.f;
#pragma unroll
        for (int dy = -1; dy <= 1; dy++) {
            int hh = h + dy;
            if ((unsigned)hh < (unsigned)H_) {
#pragma unroll
                for (int dx = -1; dx <= 1; dx++) {
                    int ww = gw + dx;
                    if ((unsigned)ww < (unsigned)W_) s += p[hh * W_ + ww];
                }
            }
        }
        s_buf[w * PB_STRIDE + c] = __float2half(p[h * W_ + gw] - s * (1.0f / 9.0f));
    }
    __syncthreads();

    uint4* dst = (uint4*)(g_th + ((size_t)(n * H_ + h) * W_ + w0) * 64);
    for (int i = tid; i < 512; i += 256) {
        int px = i >> 3, seg = i & 7;
        dst[px * 8 + seg] = *(uint4*)&s_buf[px * PB_STRIDE + seg * 8];
    }
}

// ---------------------------------------------------------------------------
// Kernel 2: out = x_l + gamma * (conv3x3(t) + b_hf)   — HMMA implicit GEMM
// grid (W/128, H, N), 8 warps: 4 (o-tiles of 16) x 2 (pixel halves of 64)
// ---------------------------------------------------------------------------
#define CT_STRIDE 72                               // halves
#define CT_BYTES  (3 * 130 * CT_STRIDE * 2)        // 56160
#define CW_BYTES  (9 * 64 * CT_STRIDE * 2)         // 82944
#define CV_SMEM   (CT_BYTES + CW_BYTES)            // 139104

__global__ void __launch_bounds__(256) conv_mma_kernel(
    const float* __restrict__ xl, const float* __restrict__ gamma,
    const float* __restrict__ bhf, float* __restrict__ out)
{
    extern __shared__ __align__(16) char smem[];
    __half* s_t = (__half*)smem;                   // [3][130][72]
    __half* s_w = (__half*)(smem + CT_BYTES);      // [9][64][72]

    const int tid = threadIdx.x, wid = tid >> 5, lane = tid & 31;
    const int w0 = blockIdx.x * 128, h = blockIdx.y, n = blockIdx.z;

    // ---- load t tile (3 h-rows x 130 pixels x 128B), zero OOB ----
    for (int i = tid; i < 3120; i += 256) {
        int hr = i / 1040, rem = i - hr * 1040;
        int px = rem >> 3, seg = rem & 7;
        int gh = h - 1 + hr, gw = w0 - 1 + px;
        uint4 v = make_uint4(0, 0, 0, 0);
        if ((unsigned)gh < (unsigned)H_ && (unsigned)gw < (unsigned)W_)
            v = *(const uint4*)(g_th + ((size_t)(n * H_ + gh) * W_ + gw) * 64 + seg * 8);
        *(uint4*)&s_t[(hr * 130 + px) * CT_STRIDE + seg * 8] = v;
    }
    // ---- load weights [9][64][72] ----
    {
        const uint4* gw4 = (const uint4*)g_W9h;
        for (int i = tid; i < 4608; i += 256) {
            int row = i >> 3, seg = i & 7;
            *(uint4*)&s_w[row * CT_STRIDE + seg * 8] = gw4[i];
        }
    }
    __syncthreads();

    const int wm = wid >> 1, wn = wid & 1;
    const int a_row = lane & 15, a_ch = lane >> 4;
    const int b_row = (lane & 7) + ((lane >> 4) << 3);
    const int b_ch  = (lane >> 3) & 1;
    const uint32_t st_b = smem_u32(s_t);
    const uint32_t sw_b = smem_u32(s_w);

    float acc[8][4];
#pragma unroll
    for (int nt = 0; nt < 8; nt++)
#pragma unroll
        for (int j = 0; j < 4; j++) acc[nt][j] = 0.f;

#pragma unroll 1
    for (int tap = 0; tap < 9; tap++) {
        const int ty = tap / 3, tx = tap - ty * 3;
        const uint32_t wbase = sw_b + ((tap * 64 + wm * 16 + a_row) * CT_STRIDE
                                       + a_ch * 8) * 2;
        const uint32_t tbase = st_b + ((ty * 130 + wn * 64 + tx + b_row) * CT_STRIDE
                                       + b_ch * 8) * 2;
#pragma unroll
        for (int ks = 0; ks < 4; ks++) {
            uint32_t aW[4];
            ldsm_x4(aW, wbase + ks * 32);
#pragma unroll
            for (int np = 0; np < 4; np++) {
                uint32_t bv[4];
                ldsm_x4(bv, tbase + np * 16 * (CT_STRIDE * 2) + ks * 32);
                mma16816(acc[2 * np],     aW, bv[0], bv[1]);
                mma16816(acc[2 * np + 1], aW, bv[2], bv[3]);
            }
        }
    }

    // ---- epilogue ----
    const int r = lane >> 2, tc = lane & 3;
    const int o0 = wm * 16 + r, o1 = o0 + 8;
    const float g0 = gamma[o0], b0 = bhf[o0];
    const float g1 = gamma[o1], b1 = bhf[o1];
    const size_t row0 = ((size_t)(n * 64 + o0) * H_ + h) * W_;
    const size_t row1 = ((size_t)(n * 64 + o1) * H_ + h) * W_;
#pragma unroll
    for (int nt = 0; nt < 8; nt++) {
        int p = w0 + wn * 64 + nt * 8 + 2 * tc;
        out[row0 + p]     = xl[row0 + p]     + g0 * (acc[nt][0] + b0);
        out[row0 + p + 1] = xl[row0 + p + 1] + g0 * (acc[nt][1] + b0);
        out[row1 + p]     = xl[row1 + p]     + g1 * (acc[nt][2] + b1);
        out[row1 + p + 1] = xl[row1 + p + 1] + g1 * (acc[nt][3] + b1);
    }
}

// ---------------------------------------------------------------------------
// Kernel 3: fused LayerNorm + 1x1 projections -> fp16 Q_l, Q_r, V^T
// ---------------------------------------------------------------------------
__device__ __forceinline__ void matvec16(
    const float* __restrict__ sx,   // [c][w], stride 65
    const float* __restrict__ sw,   // [o][c]
    const float* __restrict__ sb,   // [o]
    float* __restrict__ acc, int tid)
{
    const int og = tid >> 6;
    const int w  = tid & 63;
#pragma unroll
    for (int oo = 0; oo < 16; oo++) acc[oo] = sb[og * 16 + oo];
#pragma unroll 4
    for (int c = 0; c < 64; c += 4) {
        float v0 = sx[(c    ) * 65 + w];
        float v1 = sx[(c + 1) * 65 + w];
        float v2 = sx[(c + 2) * 65 + w];
        float v3 = sx[(c + 3) * 65 + w];
#pragma unroll
        for (int oo = 0; oo < 16; oo++) {
            float4 wv = *(const float4*)&sw[(og * 16 + oo) * 64 + c];
            acc[oo] += v0 * wv.x + v1 * wv.y + v2 * wv.z + v3 * wv.w;
        }
    }
}

__device__ __forceinline__ void store_q_half(float* acc, __half* gq, int tid, int w0)
{
    const int og = tid >> 6, w = tid & 63;
    __half2 h2[8];
#pragma unroll
    for (int oo = 0; oo < 8; oo++)
        h2[oo] = __floats2half2_rn(acc[2*oo], acc[2*oo+1]);
    uint4* dst = (uint4*)(gq + (size_t)(w0 + w) * 64 + og * 16);
    dst[0] = ((uint4*)h2)[0];
    dst[1] = ((uint4*)h2)[1];
}

__global__ void __launch_bounds__(256) proj_kernel(
    const float* __restrict__ xl, const float* __restrict__ xr,
    const float* __restrict__ nlw, const float* __restrict__ nlb,
    const float* __restrict__ nrw, const float* __restrict__ nrb,
    const float* __restrict__ Wql, const float* __restrict__ bql,
    const float* __restrict__ Wqr, const float* __restrict__ bqr,
    const float* __restrict__ Wvr, const float* __restrict__ bvr)
{
    extern __shared__ float sm[];
    float* s_xl = sm;                // 4160
    float* s_xr = sm + 4160;         // 4160
    float* s_w  = sm + 8320;         // 4096
    float* s_mu = sm + 12416;        // 128
    float* s_rs = sm + 12544;        // 128
    float* s_b  = sm + 12672;        // 64

    const int tid = threadIdx.x;
    const int w0 = blockIdx.x * 64, h = blockIdx.y, n = blockIdx.z;
    const int base = (n * 64 * H_ + h) * W_ + w0;
    const size_t pbase = (size_t)(n * H_ + h) * W_ * 64;   // halves

    for (int i = tid; i < 4096; i += 256) {
        int c = i >> 6, w = i & 63;
        s_xl[c * 65 + w] = xl[base + c * HW_ + w];
        s_xr[c * 65 + w] = xr[base + c * HW_ + w];
    }
    __syncthreads();

    if (tid < 128) {
        const float* sx = (tid < 64) ? s_xl : s_xr;
        int w = tid & 63;
        float s = 0.f, sq = 0.f;
#pragma unroll 8
        for (int c = 0; c < 64; c++) { float v = sx[c * 65 + w]; s += v; sq += v * v; }
        float mu  = s * (1.0f / 64.0f);
        float var = sq * (1.0f / 64.0f) - mu * mu;
        s_mu[tid] = mu;
        s_rs[tid] = rsqrtf(var + 1e-6f);
    }
    for (int i = tid; i < 4096; i += 256) s_w[i] = Wvr[i];
    if (tid < 64) s_b[tid] = bvr[tid];
    __syncthreads();

    // V_r from raw x_r -> transposed fp16 [c][k]
    {
        float acc[16];
        matvec16(s_xr, s_w, s_b, acc, tid);
        const int og = tid >> 6, w = tid & 63;
        __half* vp = g_Vth + pbase;
#pragma unroll
        for (int oo = 0; oo < 16; oo++)
            vp[(size_t)(og * 16 + oo) * 256 + w0 + w] = __float2half(acc[oo]);
    }
    __syncthreads();

    for (int i = tid; i < 4096; i += 256) {
        int c = i >> 6, w = i & 63;
        s_xl[c * 65 + w] = (s_xl[c * 65 + w] - s_mu[w])      * s_rs[w]      * nlw[c] + nlb[c];
        s_xr[c * 65 + w] = (s_xr[c * 65 + w] - s_mu[64 + w]) * s_rs[64 + w] * nrw[c] + nrb[c];
    }
    for (int i = tid; i < 4096; i += 256) s_w[i] = Wql[i];
    if (tid < 64) s_b[tid] = bql[tid];
    __syncthreads();

    {
        float acc[16];
        matvec16(s_xl, s_w, s_b, acc, tid);
        store_q_half(acc, g_Qlh + pbase, tid, w0);
    }
    __syncthreads();

    for (int i = tid; i < 4096; i += 256) s_w[i] = Wqr[i];
    if (tid < 64) s_b[tid] = bqr[tid];
    __syncthreads();

    {
        float acc[16];
        matvec16(s_xr, s_w, s_b, acc, tid);
        store_q_half(acc, g_Qrh + pbase, tid, w0);
    }
}

// ---------------------------------------------------------------------------
// Kernel 4: warp-MMA fp16 cross attention (mma.sync m16n8k16).
// ---------------------------------------------------------------------------
#define QL_STRIDE 72      // halves
#define VT_STRIDE 264     // halves
#define P_STRIDE  24      // halves
#define SM_QL 0
#define SM_QR (SM_QL + 256 * QL_STRIDE * 2)          // 36864
#define SM_VT (SM_QR + 256 * QL_STRIDE * 2)          // 73728
#define SM_P  (SM_VT + 64 * VT_STRIDE * 2)           // 107520
#define AT_SMEM (SM_P + 8 * 16 * P_STRIDE * 2)       // 113664

__global__ void __launch_bounds__(256, 2) attn_kernel(
    const float* __restrict__ beta, float* __restrict__ out)
{
    extern __shared__ __align__(16) char smem[];
    __half* s_ql = (__half*)(smem + SM_QL);
    __half* s_qr = (__half*)(smem + SM_QR);
    __half* s_vt = (__half*)(smem + SM_VT);

    const int tid = threadIdx.x, wid = tid >> 5, lane = tid & 31;
    const int h = blockIdx.x, n = blockIdx.y;
    const size_t pbase = (size_t)(n * H_ + h) * W_ * 64;   // halves

    {
        const uint4* gql = (const uint4*)(g_Qlh + pbase);
        const uint4* gqr = (const uint4*)(g_Qrh + pbase);
        const uint4* gvt = (const uint4*)(g_Vth + pbase);
        for (int i = tid; i < 2048; i += 256) {            // 256 rows x 8 seg
            int row = i >> 3, seg = i & 7;
            ((uint4*)(s_ql + row * QL_STRIDE))[seg] = gql[i];
            ((uint4*)(s_qr + row * QL_STRIDE))[seg] = gqr[i];
        }
        for (int i = tid; i < 2048; i += 256) {            // 64 rows x 32 seg
            int row = i >> 5, seg = i & 31;
            ((uint4*)(s_vt + row * VT_STRIDE))[seg] = gvt[i];
        }
    }
    __syncthreads();

    const uint32_t ql_b = smem_u32(s_ql);
    const uint32_t qr_b = smem_u32(s_qr);
    const uint32_t vt_b = smem_u32(s_vt);
    const uint32_t p_b  = smem_u32(smem + SM_P) + wid * (16 * P_STRIDE * 2);

    const int r  = lane >> 2;
    const int tc = lane & 3;
    const int a_row = lane & 15, a_ch = lane >> 4;
    const int b_row = (lane & 7) + ((lane >> 4) << 3);
    const int b_ch  = (lane >> 3) & 1;
    const uint32_t p_addr = p_b + a_row * (P_STRIDE * 2) + a_ch * 16;

#pragma unroll 1
    for (int qt = 0; qt < 2; qt++) {
        const int qbase = (wid * 2 + qt) * 16;

        uint32_t aQ[4][4];
#pragma unroll
        for (int ks = 0; ks < 4; ks++) {
            uint32_t addr = ql_b + (qbase + a_row) * (QL_STRIDE * 2)
                          + (ks * 16 + a_ch * 8) * 2;
            ldsm_x4(aQ[ks], addr);
        }

        float o[8][4];
#pragma unroll
        for (int nc = 0; nc < 8; nc++)
#pragma unroll
            for (int j = 0; j < 4; j++) o[nc][j] = 0.f;
        float m_r = -1e30f, m_r8 = -1e30f;
        float l_r = 0.f,    l_r8 = 0.f;

#pragma unroll 1
        for (int kk = 0; kk < 16; kk++) {
            const int kbase = kk * 16;

            float s0[4] = {0.f, 0.f, 0.f, 0.f};
            float s1[4] = {0.f, 0.f, 0.f, 0.f};
#pragma unroll
            for (int ks = 0; ks < 4; ks++) {
                uint32_t br[4];
                uint32_t addr = qr_b + (kbase + b_row) * (QL_STRIDE * 2)
                              + (ks * 16 + b_ch * 8) * 2;
                ldsm_x4(br, addr);
                mma16816(s0, aQ[ks], br[0], br[1]);
                mma16816(s1, aQ[ks], br[2], br[3]);
            }

            float cm_r  = fmaxf(fmaxf(s0[0], s0[1]), fmaxf(s1[0], s1[1]));
            float cm_r8 = fmaxf(fmaxf(s0[2], s0[3]), fmaxf(s1[2], s1[3]));
            cm_r  = fmaxf(cm_r,  __shfl_xor_sync(0xffffffff, cm_r,  1));
            cm_r  = fmaxf(cm_r,  __shfl_xor_sync(0xffffffff, cm_r,  2));
            cm_r8 = fmaxf(cm_r8, __shfl_xor_sync(0xffffffff, cm_r8, 1));
            cm_r8 = fmaxf(cm_r8, __shfl_xor_sync(0xffffffff, cm_r8, 2));
            float mn_r  = fmaxf(m_r,  cm_r  * 0.125f);
            float mn_r8 = fmaxf(m_r8, cm_r8 * 0.125f);
            float al_r  = __expf(m_r  - mn_r);
            float al_r8 = __expf(m_r8 - mn_r8);
            m_r = mn_r; m_r8 = mn_r8;

            float p00 = __expf(fmaf(s0[0], 0.125f, -mn_r));
            float p01 = __expf(fmaf(s0[1], 0.125f, -mn_r));
            float p10 = __expf(fmaf(s1[0], 0.125f, -mn_r));
            float p11 = __expf(fmaf(s1[1], 0.125f, -mn_r));
            float q00 = __expf(fmaf(s0[2], 0.125f, -mn_r8));
            float q01 = __expf(fmaf(s0[3], 0.125f, -mn_r8));
            float q10 = __expf(fmaf(s1[2], 0.125f, -mn_r8));
            float q11 = __expf(fmaf(s1[3], 0.125f, -mn_r8));
            l_r  = l_r  * al_r  + (p00 + p01) + (p10 + p11);
            l_r8 = l_r8 * al_r8 + (q00 + q01) + (q10 + q11);

#pragma unroll
            for (int nc = 0; nc < 8; nc++) {
                o[nc][0] *= al_r;  o[nc][1] *= al_r;
                o[nc][2] *= al_r8; o[nc][3] *= al_r8;
            }

            __syncwarp();
            {
                __half* pw = (__half*)(smem + SM_P) + wid * (16 * P_STRIDE);
                *(__half2*)&pw[r * P_STRIDE + 2 * tc]           = __floats2half2_rn(p00, p01);
                *(__half2*)&pw[r * P_STRIDE + 8 + 2 * tc]       = __floats2half2_rn(p10, p11);
                *(__half2*)&pw[(r + 8) * P_STRIDE + 2 * tc]     = __floats2half2_rn(q00, q01);
                *(__half2*)&pw[(r + 8) * P_STRIDE + 8 + 2 * tc] = __floats2half2_rn(q10, q11);
            }
            __syncwarp();

            uint32_t aP[4];
            ldsm_x4(aP, p_addr);

#pragma unroll
            for (int vg = 0; vg < 4; vg++) {
                uint32_t bv[4];
                uint32_t addr = vt_b + (vg * 16 + b_row) * (VT_STRIDE * 2)
                              + (kbase + b_ch * 8) * 2;
                ldsm_x4(bv, addr);
                mma16816(o[2 * vg],     aP, bv[0], bv[1]);
                mma16816(o[2 * vg + 1], aP, bv[2], bv[3]);
            }
        }

        l_r  += __shfl_xor_sync(0xffffffff, l_r,  1);
        l_r  += __shfl_xor_sync(0xffffffff, l_r,  2);
        l_r8 += __shfl_xor_sync(0xffffffff, l_r8, 1);
        l_r8 += __shfl_xor_sync(0xffffffff, l_r8, 2);
        float inv_r  = __fdividef(1.f, l_r);
        float inv_r8 = __fdividef(1.f, l_r8);

#pragma unroll
        for (int nc = 0; nc < 8; nc++) {
            int c0 = nc * 8 + 2 * tc;
            float b0 = beta[c0], b1 = beta[c0 + 1];
            size_t base0 = (((size_t)n * 64 + c0) * H_ + h) * W_ + qbase;
            out[base0 + r]            += b0 * o[nc][0] * inv_r;
            out[base0 + HW_ + r]      += b1 * o[nc][1] * inv_r;
            out[base0 + r + 8]        += b0 * o[nc][2] * inv_r8;
            out[base0 + HW_ + r + 8]  += b1 * o[nc][3] * inv_r8;
        }
    }
}

// ---------------------------------------------------------------------------
extern "C" void kernel_launch(void* const* d_in, const int* in_sizes, int n_in,
                              void* d_out, int out_size)
{
    const float* x_l  = (const float*)d_in[0];
    const float* x_r  = (const float*)d_in[1];
    const float* nl_w = (const float*)d_in[2];
    const float* nl_b = (const float*)d_in[3];
    const float* nr_w = (const float*)d_in[4];
    const float* nr_b = (const float*)d_in[5];
    const float* Wq_l = (const float*)d_in[6];
    const float* bq_l = (const float*)d_in[7];
    const float* Wq_r = (const float*)d_in[8];
    const float* bq_r = (const float*)d_in[9];
    const float* Wv_r = (const float*)d_in[10];
    const float* bv_r = (const float*)d_in[11];
    const float* beta = (const float*)d_in[12];
    const float* gamma= (const float*)d_in[13];
    const float* W_hf = (const float*)d_in[14];
    const float* b_hf = (const float*)d_in[15];
    float* out = (float*)d_out;

    cudaFuncSetAttribute(proj_kernel, cudaFuncAttributeMaxDynamicSharedMemorySize, 12736 * 4);
    cudaFuncSetAttribute(attn_kernel, cudaFuncAttributeMaxDynamicSharedMemorySize, AT_SMEM);
    cudaFuncSetAttribute(conv_mma_kernel, cudaFuncAttributeMaxDynamicSharedMemorySize, CV_SMEM);

    wconv_kernel<<<144, 256>>>(W_hf);
    pre_kernel  <<<dim3(W_/64, H_, N_), 256>>>(x_r);
    proj_kernel <<<dim3(W_/64, H_, N_), 256, 12736 * 4>>>(
        x_l, x_r, nl_w, nl_b, nr_w, nr_b, Wq_l, bq_l, Wq_r, bq_r, Wv_r, bv_r);
    conv_mma_kernel<<<dim3(W_/128, H_, N_), 256, CV_SMEM>>>(x_l, gamma, b_hf, out);
    attn_kernel <<<dim3(H_, N_), 256, AT_SMEM>>>(beta, out);
}

// round 6
// speedup vs baseline: 3.6078x; 1.1761x over previous
#include <cuda_runtime.h>
#include <cuda_fp16.h>
#include <math.h>
#include <stdint.h>

#define N_  8
#define C_  64
#define H_  128
#define W_  256
#define HW_ (H_*W_)            // 32768
#define NELEM (N_*C_*H_*W_)    // 16777216

// Scratch (device globals — no allocation in kernel_launch)
__device__ __half g_th [NELEM];   // hf input, pixel-major [n][h][w][c] fp16
__device__ __half g_W9h[9*64*64]; // conv weights [tap][o][c] fp16
__device__ __half g_Qlh[NELEM];   // [n,h,q,c]
__device__ __half g_Qrh[NELEM];   // [n,h,k,c]
__device__ __half g_Vth[NELEM];   // [n,h,c,k]

// ===========================================================================
__device__ __forceinline__ uint32_t smem_u32(const void* p) {
    uint32_t a;
    asm("{ .reg .u64 t; cvta.to.shared.u64 t, %1; cvt.u32.u64 %0, t; }"
        : "=r"(a) : "l"(p));
    return a;
}
__device__ __forceinline__ void ldsm_x4(uint32_t* r, uint32_t addr) {
    asm volatile("ldmatrix.sync.aligned.m8n8.x4.shared.b16 {%0,%1,%2,%3}, [%4];"
                 : "=r"(r[0]), "=r"(r[1]), "=r"(r[2]), "=r"(r[3]) : "r"(addr));
}
__device__ __forceinline__ void mma16816(float* d, const uint32_t* a,
                                         const uint32_t b0, const uint32_t b1) {
    asm volatile(
        "mma.sync.aligned.m16n8k16.row.col.f32.f16.f16.f32 "
        "{%0,%1,%2,%3}, {%4,%5,%6,%7}, {%8,%9}, {%0,%1,%2,%3};"
        : "+f"(d[0]), "+f"(d[1]), "+f"(d[2]), "+f"(d[3])
        : "r"(a[0]), "r"(a[1]), "r"(a[2]), "r"(a[3]), "r"(b0), "r"(b1));
}

// ---------------------------------------------------------------------------
// Kernel 0: W_hf (O,I,3,3) fp32 -> g_W9h [tap][o][c] fp16
// ---------------------------------------------------------------------------
__global__ void __launch_bounds__(256) wconv_kernel(const float* __restrict__ Whf)
{
    int i = blockIdx.x * 256 + threadIdx.x;
    if (i < 9 * 64 * 64) {
        int tap = i >> 12, rem = i & 4095;
        int o = rem >> 6, c = rem & 63;
        g_W9h[i] = __float2half(Whf[(o * 64 + c) * 9 + tap]);
    }
}

// ---------------------------------------------------------------------------
// Kernel 1: t = x_r - avgpool3x3(x_r), fp16 pixel-major out
// ---------------------------------------------------------------------------
#define PB_STRIDE 72
__global__ void __launch_bounds__(256) pre_kernel(const float* __restrict__ xr)
{
    __shared__ __half s_buf[64 * PB_STRIDE];

    const int tid = threadIdx.x;
    const int w0 = blockIdx.x * 64, h = blockIdx.y, n = blockIdx.z;
    const int cg = tid >> 6, w = tid & 63;
    const int gw = w0 + w;

#pragma unroll 1
    for (int c0 = 0; c0 < 64; c0 += 4) {
        int c = c0 + cg;
        const float* p = xr + (size_t)(n * 64 + c) * HW_;
        float s = 0.f;
#pragma unroll
        for (int dy = -1; dy <= 1; dy++) {
            int hh = h + dy;
            if ((unsigned)hh < (unsigned)H_) {
#pragma unroll
                for (int dx = -1; dx <= 1; dx++) {
                    int ww = gw + dx;
                    if ((unsigned)ww < (unsigned)W_) s += p[hh * W_ + ww];
                }
            }
        }
        s_buf[w * PB_STRIDE + c] = __float2half(p[h * W_ + gw] - s * (1.0f / 9.0f));
    }
    __syncthreads();

    uint4* dst = (uint4*)(g_th + ((size_t)(n * H_ + h) * W_ + w0) * 64);
    for (int i = tid; i < 512; i += 256) {
        int px = i >> 3, seg = i & 7;
        dst[px * 8 + seg] = *(uint4*)&s_buf[px * PB_STRIDE + seg * 8];
    }
}

// ---------------------------------------------------------------------------
// Kernel 2: out = x_l + gamma * (conv3x3(t) + b_hf) — HMMA, 2 h-rows / block
// grid (W/128, H/2, N), 8 warps: 4 (o-tiles) x 2 (pixel halves)
// ---------------------------------------------------------------------------
#define CT_STRIDE 72                               // halves
#define CT_BYTES  (4 * 130 * CT_STRIDE * 2)        // 74880
#define CW_BYTES  (9 * 64 * CT_STRIDE * 2)         // 82944
#define CV_SMEM   (CT_BYTES + CW_BYTES)            // 157824

__global__ void __launch_bounds__(256) conv_mma_kernel(
    const float* __restrict__ xl, const float* __restrict__ gamma,
    const float* __restrict__ bhf, float* __restrict__ out)
{
    extern __shared__ __align__(16) char smem[];
    __half* s_t = (__half*)smem;                   // [4][130][72]
    __half* s_w = (__half*)(smem + CT_BYTES);      // [9][64][72]

    const int tid = threadIdx.x, wid = tid >> 5, lane = tid & 31;
    const int w0 = blockIdx.x * 128, h0 = blockIdx.y * 2, n = blockIdx.z;

    // ---- load t tile (4 h-rows x 130 pixels x 128B), zero OOB ----
    for (int i = tid; i < 4160; i += 256) {
        int hr = i / 1040, rem = i - hr * 1040;
        int px = rem >> 3, seg = rem & 7;
        int gh = h0 - 1 + hr, gw = w0 - 1 + px;
        uint4 v = make_uint4(0, 0, 0, 0);
        if ((unsigned)gh < (unsigned)H_ && (unsigned)gw < (unsigned)W_)
            v = *(const uint4*)(g_th + ((size_t)(n * H_ + gh) * W_ + gw) * 64 + seg * 8);
        *(uint4*)&s_t[(hr * 130 + px) * CT_STRIDE + seg * 8] = v;
    }
    // ---- load weights [9][64][72] ----
    {
        const uint4* gw4 = (const uint4*)g_W9h;
        for (int i = tid; i < 4608; i += 256) {
            int row = i >> 3, seg = i & 7;
            *(uint4*)&s_w[row * CT_STRIDE + seg * 8] = gw4[i];
        }
    }
    __syncthreads();

    const int wm = wid >> 1, wn = wid & 1;
    const int a_row = lane & 15, a_ch = lane >> 4;
    const int b_row = (lane & 7) + ((lane >> 4) << 3);
    const int b_ch  = (lane >> 3) & 1;
    const uint32_t st_b = smem_u32(s_t);
    const uint32_t sw_b = smem_u32(s_w);

    const int r = lane >> 2, tc = lane & 3;
    const int o0 = wm * 16 + r, o1 = o0 + 8;
    const float g0 = gamma[o0], bb0 = bhf[o0];
    const float g1 = gamma[o1], bb1 = bhf[o1];

#pragma unroll 1
    for (int hrow = 0; hrow < 2; hrow++) {
        float acc[8][4];
#pragma unroll
        for (int nt = 0; nt < 8; nt++)
#pragma unroll
            for (int j = 0; j < 4; j++) acc[nt][j] = 0.f;

#pragma unroll 1
        for (int tap = 0; tap < 9; tap++) {
            const int ty = tap / 3, tx = tap - ty * 3;
            const uint32_t wbase = sw_b + ((tap * 64 + wm * 16 + a_row) * CT_STRIDE
                                           + a_ch * 8) * 2;
            const uint32_t tbase = st_b + (((hrow + ty) * 130 + wn * 64 + tx + b_row)
                                           * CT_STRIDE + b_ch * 8) * 2;
#pragma unroll
            for (int ks = 0; ks < 4; ks++) {
                uint32_t aW[4];
                ldsm_x4(aW, wbase + ks * 32);
#pragma unroll
                for (int np = 0; np < 4; np++) {
                    uint32_t bv[4];
                    ldsm_x4(bv, tbase + np * 16 * (CT_STRIDE * 2) + ks * 32);
                    mma16816(acc[2 * np],     aW, bv[0], bv[1]);
                    mma16816(acc[2 * np + 1], aW, bv[2], bv[3]);
                }
            }
        }

        const int h = h0 + hrow;
        const size_t row0 = ((size_t)(n * 64 + o0) * H_ + h) * W_;
        const size_t row1 = ((size_t)(n * 64 + o1) * H_ + h) * W_;
#pragma unroll
        for (int nt = 0; nt < 8; nt++) {
            int p = w0 + wn * 64 + nt * 8 + 2 * tc;
            out[row0 + p]     = xl[row0 + p]     + g0 * (acc[nt][0] + bb0);
            out[row0 + p + 1] = xl[row0 + p + 1] + g0 * (acc[nt][1] + bb0);
            out[row1 + p]     = xl[row1 + p]     + g1 * (acc[nt][2] + bb1);
            out[row1 + p + 1] = xl[row1 + p + 1] + g1 * (acc[nt][3] + bb1);
        }
    }
}

// ---------------------------------------------------------------------------
// Kernel 3: fused LayerNorm + 1x1 projections — HMMA version
// block per (n,h): 256 threads, full 256-px row
// ---------------------------------------------------------------------------
#define PM_NL   0
#define PM_NR   (PM_NL + 256 * 72 * 2)      // 36864
#define PM_RAW  (PM_NR + 256 * 72 * 2)      // 73728
#define PM_W    (PM_RAW + 256 * 72 * 2)     // 110592  [3][64][72]
#define PM_CW   (PM_W + 3 * 64 * 72 * 2)    // 138240  nlw,nlb,nrw,nrb fp32
#define PM_B    (PM_CW + 4 * 64 * 4)        // 139264  bql,bqr,bvr fp32
#define PM_SMEM (PM_B + 3 * 64 * 4)         // 140032

__global__ void __launch_bounds__(256) proj_mma_kernel(
    const float* __restrict__ xl, const float* __restrict__ xr,
    const float* __restrict__ nlw, const float* __restrict__ nlb,
    const float* __restrict__ nrw, const float* __restrict__ nrb,
    const float* __restrict__ Wql, const float* __restrict__ bql,
    const float* __restrict__ Wqr, const float* __restrict__ bqr,
    const float* __restrict__ Wvr, const float* __restrict__ bvr)
{
    extern __shared__ __align__(16) char smem[];
    __half* s_nl  = (__half*)(smem + PM_NL);
    __half* s_nr  = (__half*)(smem + PM_NR);
    __half* s_raw = (__half*)(smem + PM_RAW);
    __half* s_w   = (__half*)(smem + PM_W);
    float*  s_cw  = (float*)(smem + PM_CW);   // [4][64]
    float*  s_b   = (float*)(smem + PM_B);    // [3][64]

    const int tid = threadIdx.x, wid = tid >> 5, lane = tid & 31;
    const int h = blockIdx.x, n = blockIdx.y;
    const size_t base0 = (size_t)(n * 64 * H_ + h) * W_ + tid;   // c=0, pixel tid
    const size_t pbase = (size_t)(n * H_ + h) * W_ * 64;         // halves

    // ---- param loads ----
    if (tid < 64) {
        s_cw[tid]       = nlw[tid];
        s_cw[64 + tid]  = nlb[tid];
        s_cw[128 + tid] = nrw[tid];
        s_cw[192 + tid] = nrb[tid];
        s_b[tid]        = bql[tid];
        s_b[64 + tid]   = bqr[tid];
        s_b[128 + tid]  = bvr[tid];
    }

    // ---- x_r: load 64 channels of pixel tid, LN stats ----
    {
        float v[64];
        float s = 0.f, sq = 0.f;
#pragma unroll
        for (int c = 0; c < 64; c++) {
            v[c] = xr[base0 + (size_t)c * HW_];
            s += v[c]; sq += v[c] * v[c];
        }
        float mu = s * (1.0f / 64.0f);
        float rs = rsqrtf(sq * (1.0f / 64.0f) - mu * mu + 1e-6f);
        __syncthreads();   // s_cw ready
#pragma unroll
        for (int c = 0; c < 64; c += 2) {
            *(__half2*)&s_raw[tid * 72 + c] = __floats2half2_rn(v[c], v[c + 1]);
            float n0 = (v[c]     - mu) * rs * s_cw[128 + c]     + s_cw[192 + c];
            float n1 = (v[c + 1] - mu) * rs * s_cw[128 + c + 1] + s_cw[192 + c + 1];
            *(__half2*)&s_nr[tid * 72 + c] = __floats2half2_rn(n0, n1);
        }
    }
    // ---- x_l ----
    {
        float v[64];
        float s = 0.f, sq = 0.f;
#pragma unroll
        for (int c = 0; c < 64; c++) {
            v[c] = xl[base0 + (size_t)c * HW_];
            s += v[c]; sq += v[c] * v[c];
        }
        float mu = s * (1.0f / 64.0f);
        float rs = rsqrtf(sq * (1.0f / 64.0f) - mu * mu + 1e-6f);
#pragma unroll
        for (int c = 0; c < 64; c += 2) {
            float n0 = (v[c]     - mu) * rs * s_cw[c]     + s_cw[64 + c];
            float n1 = (v[c + 1] - mu) * rs * s_cw[c + 1] + s_cw[64 + c + 1];
            *(__half2*)&s_nl[tid * 72 + c] = __floats2half2_rn(n0, n1);
        }
    }
    // ---- weights fp32 -> fp16 smem [mat][o][72] ----
    for (int i = tid; i < 4096; i += 256) {
        int o = i >> 6, c = i & 63;
        s_w[o * 72 + c]              = __float2half(Wql[i]);
        s_w[(64 + o) * 72 + c]       = __float2half(Wqr[i]);
        s_w[(128 + o) * 72 + c]      = __float2half(Wvr[i]);
    }
    __syncthreads();

    const int a_row = lane & 15, a_ch = lane >> 4;
    const int b_row = (lane & 7) + ((lane >> 4) << 3);
    const int b_ch  = (lane >> 3) & 1;
    const int r = lane >> 2, tc = lane & 3;
    const uint32_t w_b = smem_u32(s_w);

    // ---- G1/G2: Q = norm @ W^T, M=256 (warp: 32 px), N=64, K=64 ----
#pragma unroll 1
    for (int g = 0; g < 2; g++) {
        const uint32_t x_b = smem_u32(g ? s_nr : s_nl);
        __half* gq = (g ? g_Qrh : g_Qlh) + pbase;
#pragma unroll 1
        for (int mt = 0; mt < 2; mt++) {
            const int px0 = wid * 32 + mt * 16;
            uint32_t aA[4][4];
#pragma unroll
            for (int ks = 0; ks < 4; ks++)
                ldsm_x4(aA[ks], x_b + ((px0 + a_row) * 72 + ks * 16 + a_ch * 8) * 2);

            float acc[8][4];
#pragma unroll
            for (int nt = 0; nt < 8; nt++)
#pragma unroll
                for (int j = 0; j < 4; j++) acc[nt][j] = 0.f;

#pragma unroll
            for (int nt4 = 0; nt4 < 4; nt4++) {
                const uint32_t wb = w_b + ((g * 64 + nt4 * 16 + b_row) * 72
                                           + b_ch * 8) * 2;
#pragma unroll
                for (int ks = 0; ks < 4; ks++) {
                    uint32_t bw[4];
                    ldsm_x4(bw, wb + ks * 32);
                    mma16816(acc[2 * nt4],     aA[ks], bw[0], bw[1]);
                    mma16816(acc[2 * nt4 + 1], aA[ks], bw[2], bw[3]);
                }
            }
#pragma unroll
            for (int nc = 0; nc < 8; nc++) {
                int o = nc * 8 + 2 * tc;
                float b0 = s_b[g * 64 + o], b1 = s_b[g * 64 + o + 1];
                *(__half2*)&gq[(size_t)(px0 + r) * 64 + o] =
                    __floats2half2_rn(acc[nc][0] + b0, acc[nc][1] + b1);
                *(__half2*)&gq[(size_t)(px0 + r + 8) * 64 + o] =
                    __floats2half2_rn(acc[nc][2] + b0, acc[nc][3] + b1);
            }
        }
    }

    // ---- G3: V^T = W_v @ raw^T, M=64 (warp: 16 o), N=256 (warp: 128 px) ----
    {
        const int mt = wid >> 1, nh = wid & 1;
        const uint32_t raw_b = smem_u32(s_raw);
        uint32_t aA[4][4];
#pragma unroll
        for (int ks = 0; ks < 4; ks++)
            ldsm_x4(aA[ks], w_b + ((128 + mt * 16 + a_row) * 72 + ks * 16
                                   + a_ch * 8) * 2);

        float acc[16][4];
#pragma unroll
        for (int j = 0; j < 16; j++)
#pragma unroll
            for (int k = 0; k < 4; k++) acc[j][k] = 0.f;

#pragma unroll
        for (int nt = 0; nt < 8; nt++) {
            const uint32_t bb = raw_b + ((nh * 128 + nt * 16 + b_row) * 72
                                         + b_ch * 8) * 2;
#pragma unroll
            for (int ks = 0; ks < 4; ks++) {
                uint32_t bv[4];
                ldsm_x4(bv, bb + ks * 32);
                mma16816(acc[2 * nt],     aA[ks], bv[0], bv[1]);
                mma16816(acc[2 * nt + 1], aA[ks], bv[2], bv[3]);
            }
        }

        const int o0 = mt * 16 + r, o1 = o0 + 8;
        const float b0 = s_b[128 + o0], b1 = s_b[128 + o1];
        __half* gvt = g_Vth + pbase;
#pragma unroll
        for (int j = 0; j < 16; j++) {
            int px = nh * 128 + j * 8 + 2 * tc;
            *(__half2*)&gvt[(size_t)o0 * 256 + px] =
                __floats2half2_rn(acc[j][0] + b0, acc[j][1] + b0);
            *(__half2*)&gvt[(size_t)o1 * 256 + px] =
                __floats2half2_rn(acc[j][2] + b1, acc[j][3] + b1);
        }
    }
}

// ---------------------------------------------------------------------------
// Kernel 4: warp-MMA fp16 cross attention (mma.sync m16n8k16).
// ---------------------------------------------------------------------------
#define QL_STRIDE 72      // halves
#define VT_STRIDE 264     // halves
#define P_STRIDE  24      // halves
#define SM_QL 0
#define SM_QR (SM_QL + 256 * QL_STRIDE * 2)          // 36864
#define SM_VT (SM_QR + 256 * QL_STRIDE * 2)          // 73728
#define SM_P  (SM_VT + 64 * VT_STRIDE * 2)           // 107520
#define AT_SMEM (SM_P + 8 * 16 * P_STRIDE * 2)       // 113664

__global__ void __launch_bounds__(256, 2) attn_kernel(
    const float* __restrict__ beta, float* __restrict__ out)
{
    extern __shared__ __align__(16) char smem[];
    __half* s_ql = (__half*)(smem + SM_QL);
    __half* s_qr = (__half*)(smem + SM_QR);
    __half* s_vt = (__half*)(smem + SM_VT);

    const int tid = threadIdx.x, wid = tid >> 5, lane = tid & 31;
    const int h = blockIdx.x, n = blockIdx.y;
    const size_t pbase = (size_t)(n * H_ + h) * W_ * 64;   // halves

    {
        const uint4* gql = (const uint4*)(g_Qlh + pbase);
        const uint4* gqr = (const uint4*)(g_Qrh + pbase);
        const uint4* gvt = (const uint4*)(g_Vth + pbase);
        for (int i = tid; i < 2048; i += 256) {
            int row = i >> 3, seg = i & 7;
            ((uint4*)(s_ql + row * QL_STRIDE))[seg] = gql[i];
            ((uint4*)(s_qr + row * QL_STRIDE))[seg] = gqr[i];
        }
        for (int i = tid; i < 2048; i += 256) {
            int row = i >> 5, seg = i & 31;
            ((uint4*)(s_vt + row * VT_STRIDE))[seg] = gvt[i];
        }
    }
    __syncthreads();

    const uint32_t ql_b = smem_u32(s_ql);
    const uint32_t qr_b = smem_u32(s_qr);
    const uint32_t vt_b = smem_u32(s_vt);
    const uint32_t p_b  = smem_u32(smem + SM_P) + wid * (16 * P_STRIDE * 2);

    const int r  = lane >> 2;
    const int tc = lane & 3;
    const int a_row = lane & 15, a_ch = lane >> 4;
    const int b_row = (lane & 7) + ((lane >> 4) << 3);
    const int b_ch  = (lane >> 3) & 1;
    const uint32_t p_addr = p_b + a_row * (P_STRIDE * 2) + a_ch * 16;

#pragma unroll 1
    for (int qt = 0; qt < 2; qt++) {
        const int qbase = (wid * 2 + qt) * 16;

        uint32_t aQ[4][4];
#pragma unroll
        for (int ks = 0; ks < 4; ks++) {
            uint32_t addr = ql_b + (qbase + a_row) * (QL_STRIDE * 2)
                          + (ks * 16 + a_ch * 8) * 2;
            ldsm_x4(aQ[ks], addr);
        }

        float o[8][4];
#pragma unroll
        for (int nc = 0; nc < 8; nc++)
#pragma unroll
            for (int j = 0; j < 4; j++) o[nc][j] = 0.f;
        float m_r = -1e30f, m_r8 = -1e30f;
        float l_r = 0.f,    l_r8 = 0.f;

#pragma unroll 1
        for (int kk = 0; kk < 16; kk++) {
            const int kbase = kk * 16;

            float s0[4] = {0.f, 0.f, 0.f, 0.f};
            float s1[4] = {0.f, 0.f, 0.f, 0.f};
#pragma unroll
            for (int ks = 0; ks < 4; ks++) {
                uint32_t br[4];
                uint32_t addr = qr_b + (kbase + b_row) * (QL_STRIDE * 2)
                              + (ks * 16 + b_ch * 8) * 2;
                ldsm_x4(br, addr);
                mma16816(s0, aQ[ks], br[0], br[1]);
                mma16816(s1, aQ[ks], br[2], br[3]);
            }

            float cm_r  = fmaxf(fmaxf(s0[0], s0[1]), fmaxf(s1[0], s1[1]));
            float cm_r8 = fmaxf(fmaxf(s0[2], s0[3]), fmaxf(s1[2], s1[3]));
            cm_r  = fmaxf(cm_r,  __shfl_xor_sync(0xffffffff, cm_r,  1));
            cm_r  = fmaxf(cm_r,  __shfl_xor_sync(0xffffffff, cm_r,  2));
            cm_r8 = fmaxf(cm_r8, __shfl_xor_sync(0xffffffff, cm_r8, 1));
            cm_r8 = fmaxf(cm_r8, __shfl_xor_sync(0xffffffff, cm_r8, 2));
            float mn_r  = fmaxf(m_r,  cm_r  * 0.125f);
            float mn_r8 = fmaxf(m_r8, cm_r8 * 0.125f);
            float al_r  = __expf(m_r  - mn_r);
            float al_r8 = __expf(m_r8 - mn_r8);
            m_r = mn_r; m_r8 = mn_r8;

            float p00 = __expf(fmaf(s0[0], 0.125f, -mn_r));
            float p01 = __expf(fmaf(s0[1], 0.125f, -mn_r));
            float p10 = __expf(fmaf(s1[0], 0.125f, -mn_r));
            float p11 = __expf(fmaf(s1[1], 0.125f, -mn_r));
            float q00 = __expf(fmaf(s0[2], 0.125f, -mn_r8));
            float q01 = __expf(fmaf(s0[3], 0.125f, -mn_r8));
            float q10 = __expf(fmaf(s1[2], 0.125f, -mn_r8));
            float q11 = __expf(fmaf(s1[3], 0.125f, -mn_r8));
            l_r  = l_r  * al_r  + (p00 + p01) + (p10 + p11);
            l_r8 = l_r8 * al_r8 + (q00 + q01) + (q10 + q11);

#pragma unroll
            for (int nc = 0; nc < 8; nc++) {
                o[nc][0] *= al_r;  o[nc][1] *= al_r;
                o[nc][2] *= al_r8; o[nc][3] *= al_r8;
            }

            __syncwarp();
            {
                __half* pw = (__half*)(smem + SM_P) + wid * (16 * P_STRIDE);
                *(__half2*)&pw[r * P_STRIDE + 2 * tc]           = __floats2half2_rn(p00, p01);
                *(__half2*)&pw[r * P_STRIDE + 8 + 2 * tc]       = __floats2half2_rn(p10, p11);
                *(__half2*)&pw[(r + 8) * P_STRIDE + 2 * tc]     = __floats2half2_rn(q00, q01);
                *(__half2*)&pw[(r + 8) * P_STRIDE + 8 + 2 * tc] = __floats2half2_rn(q10, q11);
            }
            __syncwarp();

            uint32_t aP[4];
            ldsm_x4(aP, p_addr);

#pragma unroll
            for (int vg = 0; vg < 4; vg++) {
                uint32_t bv[4];
                uint32_t addr = vt_b + (vg * 16 + b_row) * (VT_STRIDE * 2)
                              + (kbase + b_ch * 8) * 2;
                ldsm_x4(bv, addr);
                mma16816(o[2 * vg],     aP, bv[0], bv[1]);
                mma16816(o[2 * vg + 1], aP, bv[2], bv[3]);
            }
        }

        l_r  += __shfl_xor_sync(0xffffffff, l_r,  1);
        l_r  += __shfl_xor_sync(0xffffffff, l_r,  2);
        l_r8 += __shfl_xor_sync(0xffffffff, l_r8, 1);
        l_r8 += __shfl_xor_sync(0xffffffff, l_r8, 2);
        float inv_r  = __fdividef(1.f, l_r);
        float inv_r8 = __fdividef(1.f, l_r8);

#pragma unroll
        for (int nc = 0; nc < 8; nc++) {
            int c0 = nc * 8 + 2 * tc;
            float b0 = beta[c0], b1 = beta[c0 + 1];
            size_t base0 = (((size_t)n * 64 + c0) * H_ + h) * W_ + qbase;
            out[base0 + r]            += b0 * o[nc][0] * inv_r;
            out[base0 + HW_ + r]      += b1 * o[nc][1] * inv_r;
            out[base0 + r + 8]        += b0 * o[nc][2] * inv_r8;
            out[base0 + HW_ + r + 8]  += b1 * o[nc][3] * inv_r8;
        }
    }
}

// ---------------------------------------------------------------------------
extern "C" void kernel_launch(void* const* d_in, const int* in_sizes, int n_in,
                              void* d_out, int out_size)
{
    const float* x_l  = (const float*)d_in[0];
    const float* x_r  = (const float*)d_in[1];
    const float* nl_w = (const float*)d_in[2];
    const float* nl_b = (const float*)d_in[3];
    const float* nr_w = (const float*)d_in[4];
    const float* nr_b = (const float*)d_in[5];
    const float* Wq_l = (const float*)d_in[6];
    const float* bq_l = (const float*)d_in[7];
    const float* Wq_r = (const float*)d_in[8];
    const float* bq_r = (const float*)d_in[9];
    const float* Wv_r = (const float*)d_in[10];
    const float* bv_r = (const float*)d_in[11];
    const float* beta = (const float*)d_in[12];
    const float* gamma= (const float*)d_in[13];
    const float* W_hf = (const float*)d_in[14];
    const float* b_hf = (const float*)d_in[15];
    float* out = (float*)d_out;

    cudaFuncSetAttribute(proj_mma_kernel, cudaFuncAttributeMaxDynamicSharedMemorySize, PM_SMEM);
    cudaFuncSetAttribute(attn_kernel, cudaFuncAttributeMaxDynamicSharedMemorySize, AT_SMEM);
    cudaFuncSetAttribute(conv_mma_kernel, cudaFuncAttributeMaxDynamicSharedMemorySize, CV_SMEM);

    wconv_kernel<<<144, 256>>>(W_hf);
    pre_kernel  <<<dim3(W_/64, H_, N_), 256>>>(x_r);
    proj_mma_kernel<<<dim3(H_, N_), 256, PM_SMEM>>>(
        x_l, x_r, nl_w, nl_b, nr_w, nr_b, Wq_l, bq_l, Wq_r, bq_r, Wv_r, bv_r);
    conv_mma_kernel<<<dim3(W_/128, H_/2, N_), 256, CV_SMEM>>>(x_l, gamma, b_hf, out);
    attn_kernel <<<dim3(H_, N_), 256, AT_SMEM>>>(beta, out);
}

// round 11
// speedup vs baseline: 4.8511x; 1.3446x over previous
#include <cuda_runtime.h>
#include <cuda_fp16.h>
#include <math.h>
#include <stdint.h>

#define N_  8
#define C_  64
#define H_  128
#define W_  256
#define HW_ (H_*W_)            // 32768
#define NELEM (N_*C_*H_*W_)    // 16777216

// Scratch (device globals — no allocation in kernel_launch)
__device__ __half g_th [NELEM];   // hf input, pixel-major [n][h][w][c] fp16
__device__ __half g_W9h[9*64*64]; // conv weights [tap][o][c] fp16
__device__ __half g_Qlh[NELEM];   // [n,h,q,c]
__device__ __half g_Qrh[NELEM];   // [n,h,k,c]
__device__ __half g_Vth[NELEM];   // [n,h,c,k]

// ===========================================================================
__device__ __forceinline__ uint32_t smem_u32(const void* p) {
    uint32_t a;
    asm("{ .reg .u64 t; cvta.to.shared.u64 t, %1; cvt.u32.u64 %0, t; }"
        : "=r"(a) : "l"(p));
    return a;
}
__device__ __forceinline__ void ldsm_x4(uint32_t* r, uint32_t addr) {
    asm volatile("ldmatrix.sync.aligned.m8n8.x4.shared.b16 {%0,%1,%2,%3}, [%4];"
                 : "=r"(r[0]), "=r"(r[1]), "=r"(r[2]), "=r"(r[3]) : "r"(addr));
}
__device__ __forceinline__ void mma16816(float* d, const uint32_t* a,
                                         const uint32_t b0, const uint32_t b1) {
    asm volatile(
        "mma.sync.aligned.m16n8k16.row.col.f32.f16.f16.f32 "
        "{%0,%1,%2,%3}, {%4,%5,%6,%7}, {%8,%9}, {%0,%1,%2,%3};"
        : "+f"(d[0]), "+f"(d[1]), "+f"(d[2]), "+f"(d[3])
        : "r"(a[0]), "r"(a[1]), "r"(a[2]), "r"(a[3]), "r"(b0), "r"(b1));
}

// ---------------------------------------------------------------------------
// Kernel 0: W_hf (O,I,3,3) fp32 -> g_W9h [tap][o][c] fp16
// ---------------------------------------------------------------------------
__global__ void __launch_bounds__(256) wconv_kernel(const float* __restrict__ Whf)
{
    int i = blockIdx.x * 256 + threadIdx.x;
    if (i < 9 * 64 * 64) {
        int tap = i >> 12, rem = i & 4095;
        int o = rem >> 6, c = rem & 63;
        g_W9h[i] = __float2half(Whf[(o * 64 + c) * 9 + tap]);
    }
}

// ---------------------------------------------------------------------------
// Kernel 1: t = x_r - avgpool3x3(x_r), fp16 pixel-major out
// ---------------------------------------------------------------------------
#define PB_STRIDE 72
__global__ void __launch_bounds__(256) pre_kernel(const float* __restrict__ xr)
{
    __shared__ __half s_buf[64 * PB_STRIDE];

    const int tid = threadIdx.x;
    const int w0 = blockIdx.x * 64, h = blockIdx.y, n = blockIdx.z;
    const int cg = tid >> 6, w = tid & 63;
    const int gw = w0 + w;

#pragma unroll 1
    for (int c0 = 0; c0 < 64; c0 += 4) {
        int c = c0 + cg;
        const float* p = xr + (size_t)(n * 64 + c) * HW_;
        float s = 0.f;
#pragma unroll
        for (int dy = -1; dy <= 1; dy++) {
            int hh = h + dy;
            if ((unsigned)hh < (unsigned)H_) {
#pragma unroll
                for (int dx = -1; dx <= 1; dx++) {
                    int ww = gw + dx;
                    if ((unsigned)ww < (unsigned)W_) s += p[hh * W_ + ww];
                }
            }
        }
        s_buf[w * PB_STRIDE + c] = __float2half(p[h * W_ + gw] - s * (1.0f / 9.0f));
    }
    __syncthreads();

    uint4* dst = (uint4*)(g_th + ((size_t)(n * H_ + h) * W_ + w0) * 64);
    for (int i = tid; i < 512; i += 256) {
        int px = i >> 3, seg = i & 7;
        dst[px * 8 + seg] = *(uint4*)&s_buf[px * PB_STRIDE + seg * 8];
    }
}

// ---------------------------------------------------------------------------
// Kernel 2: out = x_l + gamma * (conv3x3(t) + b_hf) — HMMA implicit GEMM
// grid (W/128, H, N). smem: swizzled t-tile only (48.75KB) -> 4 CTA/SM.
// Weights: per-lane A-fragments straight from global (L1-resident).
// ---------------------------------------------------------------------------
#define CV_SMEM (3 * 130 * 128)                   // 49920 bytes

__global__ void __launch_bounds__(256, 4) conv_mma_kernel(
    const float* __restrict__ xl, const float* __restrict__ gamma,
    const float* __restrict__ bhf, float* __restrict__ out)
{
    extern __shared__ __align__(16) char smem[];

    const int tid = threadIdx.x, wid = tid >> 5, lane = tid & 31;
    const int w0 = blockIdx.x * 128, h = blockIdx.y, n = blockIdx.z;

    // ---- load t tile (3 h-rows x 130 px x 128B), XOR-swizzled, zero OOB ----
    for (int i = tid; i < 3120; i += 256) {
        int hr = i / 1040, rem = i - hr * 1040;
        int px = rem >> 3, seg = rem & 7;
        int row = hr * 130 + px;
        int gh = h - 1 + hr, gw = w0 - 1 + px;
        uint4 v = make_uint4(0, 0, 0, 0);
        if ((unsigned)gh < (unsigned)H_ && (unsigned)gw < (unsigned)W_)
            v = *(const uint4*)(g_th + ((size_t)(n * H_ + gh) * W_ + gw) * 64 + seg * 8);
        *(uint4*)(smem + row * 128 + ((seg ^ (row & 7)) << 4)) = v;
    }
    __syncthreads();

    const int wm = wid >> 1, wn = wid & 1;
    const int r = lane >> 2, tc = lane & 3;
    const int b_row = (lane & 7) + ((lane >> 4) << 3);
    const int b_ch  = (lane >> 3) & 1;
    const uint32_t st_b = smem_u32(smem);

    float acc[8][4];
#pragma unroll
    for (int nt = 0; nt < 8; nt++)
#pragma unroll
        for (int j = 0; j < 4; j++) acc[nt][j] = 0.f;

    const int wrow0 = wm * 16 + r;             // weight o-row (fragment)
    const int wcol0 = 2 * tc;                  // weight c-col base

#pragma unroll 1
    for (int tap = 0; tap < 9; tap++) {
        const int ty = tap / 3, tx = tap - ty * 3;

        // A-fragments of weights, direct from global (uint32 = 2 halves)
        const uint32_t* wp = (const uint32_t*)(g_W9h + tap * 4096);
        uint32_t aW[4][4];
#pragma unroll
        for (int ks = 0; ks < 4; ks++) {
            int col = ks * 16 + wcol0;
            aW[ks][0] = wp[(wrow0 * 64 + col) >> 1];
            aW[ks][1] = wp[((wrow0 + 8) * 64 + col) >> 1];
            aW[ks][2] = wp[(wrow0 * 64 + col + 8) >> 1];
            aW[ks][3] = wp[((wrow0 + 8) * 64 + col + 8) >> 1];
        }

#pragma unroll
        for (int ks = 0; ks < 4; ks++) {
#pragma unroll
            for (int np = 0; np < 4; np++) {
                int row_t = ty * 130 + wn * 64 + tx + np * 16 + b_row;
                int chunk = ks * 2 + b_ch;
                uint32_t addr = st_b + row_t * 128 + ((chunk ^ (row_t & 7)) << 4);
                uint32_t bv[4];
                ldsm_x4(bv, addr);
                mma16816(acc[2 * np],     aW[ks], bv[0], bv[1]);
                mma16816(acc[2 * np + 1], aW[ks], bv[2], bv[3]);
            }
        }
    }

    // ---- epilogue ----
    const int o0 = wm * 16 + r, o1 = o0 + 8;
    const float g0 = gamma[o0], bb0 = bhf[o0];
    const float g1 = gamma[o1], bb1 = bhf[o1];
    const size_t row0 = ((size_t)(n * 64 + o0) * H_ + h) * W_;
    const size_t row1 = ((size_t)(n * 64 + o1) * H_ + h) * W_;
#pragma unroll
    for (int nt = 0; nt < 8; nt++) {
        int p = w0 + wn * 64 + nt * 8 + 2 * tc;
        out[row0 + p]     = xl[row0 + p]     + g0 * (acc[nt][0] + bb0);
        out[row0 + p + 1] = xl[row0 + p + 1] + g0 * (acc[nt][1] + bb0);
        out[row1 + p]     = xl[row1 + p]     + g1 * (acc[nt][2] + bb1);
        out[row1 + p + 1] = xl[row1 + p + 1] + g1 * (acc[nt][3] + bb1);
    }
}

// ---------------------------------------------------------------------------
// Kernel 3: fused LayerNorm + 1x1 projections — HMMA version
// ---------------------------------------------------------------------------
#define PM_NL   0
#define PM_NR   (PM_NL + 256 * 72 * 2)      // 36864
#define PM_RAW  (PM_NR + 256 * 72 * 2)      // 73728
#define PM_W    (PM_RAW + 256 * 72 * 2)     // 110592  [3][64][72]
#define PM_CW   (PM_W + 3 * 64 * 72 * 2)    // 138240
#define PM_B    (PM_CW + 4 * 64 * 4)        // 139264
#define PM_SMEM (PM_B + 3 * 64 * 4)         // 140032

__global__ void __launch_bounds__(256) proj_mma_kernel(
    const float* __restrict__ xl, const float* __restrict__ xr,
    const float* __restrict__ nlw, const float* __restrict__ nlb,
    const float* __restrict__ nrw, const float* __restrict__ nrb,
    const float* __restrict__ Wql, const float* __restrict__ bql,
    const float* __restrict__ Wqr, const float* __restrict__ bqr,
    const float* __restrict__ Wvr, const float* __restrict__ bvr)
{
    extern __shared__ __align__(16) char smem[];
    __half* s_nl  = (__half*)(smem + PM_NL);
    __half* s_nr  = (__half*)(smem + PM_NR);
    __half* s_raw = (__half*)(smem + PM_RAW);
    __half* s_w   = (__half*)(smem + PM_W);
    float*  s_cw  = (float*)(smem + PM_CW);
    float*  s_b   = (float*)(smem + PM_B);

    const int tid = threadIdx.x, wid = tid >> 5, lane = tid & 31;
    const int h = blockIdx.x, n = blockIdx.y;
    const size_t base0 = (size_t)(n * 64 * H_ + h) * W_ + tid;
    const size_t pbase = (size_t)(n * H_ + h) * W_ * 64;

    if (tid < 64) {
        s_cw[tid]       = nlw[tid];
        s_cw[64 + tid]  = nlb[tid];
        s_cw[128 + tid] = nrw[tid];
        s_cw[192 + tid] = nrb[tid];
        s_b[tid]        = bql[tid];
        s_b[64 + tid]   = bqr[tid];
        s_b[128 + tid]  = bvr[tid];
    }

    {
        float v[64];
        float s = 0.f, sq = 0.f;
#pragma unroll
        for (int c = 0; c < 64; c++) {
            v[c] = xr[base0 + (size_t)c * HW_];
            s += v[c]; sq += v[c] * v[c];
        }
        float mu = s * (1.0f / 64.0f);
        float rs = rsqrtf(sq * (1.0f / 64.0f) - mu * mu + 1e-6f);
        __syncthreads();
#pragma unroll
        for (int c = 0; c < 64; c += 2) {
            *(__half2*)&s_raw[tid * 72 + c] = __floats2half2_rn(v[c], v[c + 1]);
            float n0 = (v[c]     - mu) * rs * s_cw[128 + c]     + s_cw[192 + c];
            float n1 = (v[c + 1] - mu) * rs * s_cw[128 + c + 1] + s_cw[192 + c + 1];
            *(__half2*)&s_nr[tid * 72 + c] = __floats2half2_rn(n0, n1);
        }
    }
    {
        float v[64];
        float s = 0.f, sq = 0.f;
#pragma unroll
        for (int c = 0; c < 64; c++) {
            v[c] = xl[base0 + (size_t)c * HW_];
            s += v[c]; sq += v[c] * v[c];
        }
        float mu = s * (1.0f / 64.0f);
        float rs = rsqrtf(sq * (1.0f / 64.0f) - mu * mu + 1e-6f);
#pragma unroll
        for (int c = 0; c < 64; c += 2) {
            float n0 = (v[c]     - mu) * rs * s_cw[c]     + s_cw[64 + c];
            float n1 = (v[c + 1] - mu) * rs * s_cw[c + 1] + s_cw[64 + c + 1];
            *(__half2*)&s_nl[tid * 72 + c] = __floats2half2_rn(n0, n1);
        }
    }
    for (int i = tid; i < 4096; i += 256) {
        int o = i >> 6, c = i & 63;
        s_w[o * 72 + c]         = __float2half(Wql[i]);
        s_w[(64 + o) * 72 + c]  = __float2half(Wqr[i]);
        s_w[(128 + o) * 72 + c] = __float2half(Wvr[i]);
    }
    __syncthreads();

    const int a_row = lane & 15, a_ch = lane >> 4;
    const int b_row = (lane & 7) + ((lane >> 4) << 3);
    const int b_ch  = (lane >> 3) & 1;
    const int r = lane >> 2, tc = lane & 3;
    const uint32_t w_b = smem_u32(s_w);

#pragma unroll 1
    for (int g = 0; g < 2; g++) {
        const uint32_t x_b = smem_u32(g ? s_nr : s_nl);
        __half* gq = (g ? g_Qrh : g_Qlh) + pbase;
#pragma unroll 1
        for (int mt = 0; mt < 2; mt++) {
            const int px0 = wid * 32 + mt * 16;
            uint32_t aA[4][4];
#pragma unroll
            for (int ks = 0; ks < 4; ks++)
                ldsm_x4(aA[ks], x_b + ((px0 + a_row) * 72 + ks * 16 + a_ch * 8) * 2);

            float acc[8][4];
#pragma unroll
            for (int nt = 0; nt < 8; nt++)
#pragma unroll
                for (int j = 0; j < 4; j++) acc[nt][j] = 0.f;

#pragma unroll
            for (int nt4 = 0; nt4 < 4; nt4++) {
                const uint32_t wb = w_b + ((g * 64 + nt4 * 16 + b_row) * 72
                                           + b_ch * 8) * 2;
#pragma unroll
                for (int ks = 0; ks < 4; ks++) {
                    uint32_t bw[4];
                    ldsm_x4(bw, wb + ks * 32);
                    mma16816(acc[2 * nt4],     aA[ks], bw[0], bw[1]);
                    mma16816(acc[2 * nt4 + 1], aA[ks], bw[2], bw[3]);
                }
            }
#pragma unroll
            for (int nc = 0; nc < 8; nc++) {
                int o = nc * 8 + 2 * tc;
                float b0 = s_b[g * 64 + o], b1 = s_b[g * 64 + o + 1];
                *(__half2*)&gq[(size_t)(px0 + r) * 64 + o] =
                    __floats2half2_rn(acc[nc][0] + b0, acc[nc][1] + b1);
                *(__half2*)&gq[(size_t)(px0 + r + 8) * 64 + o] =
                    __floats2half2_rn(acc[nc][2] + b0, acc[nc][3] + b1);
            }
        }
    }

    {
        const int mt = wid >> 1, nh = wid & 1;
        const uint32_t raw_b = smem_u32(s_raw);
        uint32_t aA[4][4];
#pragma unroll
        for (int ks = 0; ks < 4; ks++)
            ldsm_x4(aA[ks], w_b + ((128 + mt * 16 + a_row) * 72 + ks * 16
                                   + a_ch * 8) * 2);

        float acc[16][4];
#pragma unroll
        for (int j = 0; j < 16; j++)
#pragma unroll
            for (int k = 0; k < 4; k++) acc[j][k] = 0.f;

#pragma unroll
        for (int nt = 0; nt < 8; nt++) {
            const uint32_t bb = raw_b + ((nh * 128 + nt * 16 + b_row) * 72
                                         + b_ch * 8) * 2;
#pragma unroll
            for (int ks = 0; ks < 4; ks++) {
                uint32_t bv[4];
                ldsm_x4(bv, bb + ks * 32);
                mma16816(acc[2 * nt],     aA[ks], bv[0], bv[1]);
                mma16816(acc[2 * nt + 1], aA[ks], bv[2], bv[3]);
            }
        }

        const int o0 = mt * 16 + r, o1 = o0 + 8;
        const float b0 = s_b[128 + o0], b1 = s_b[128 + o1];
        __half* gvt = g_Vth + pbase;
#pragma unroll
        for (int j = 0; j < 16; j++) {
            int px = nh * 128 + j * 8 + 2 * tc;
            *(__half2*)&gvt[(size_t)o0 * 256 + px] =
                __floats2half2_rn(acc[j][0] + b0, acc[j][1] + b0);
            *(__half2*)&gvt[(size_t)o1 * 256 + px] =
                __floats2half2_rn(acc[j][2] + b1, acc[j][3] + b1);
        }
    }
}

// ---------------------------------------------------------------------------
// Kernel 4: warp-MMA fp16 cross attention (mma.sync m16n8k16).
// ---------------------------------------------------------------------------
#define QL_STRIDE 72      // halves
#define VT_STRIDE 264     // halves
#define P_STRIDE  24      // halves
#define SM_QL 0
#define SM_QR (SM_QL + 256 * QL_STRIDE * 2)          // 36864
#define SM_VT (SM_QR + 256 * QL_STRIDE * 2)          // 73728
#define SM_P  (SM_VT + 64 * VT_STRIDE * 2)           // 107520
#define AT_SMEM (SM_P + 8 * 16 * P_STRIDE * 2)       // 113664

__global__ void __launch_bounds__(256, 2) attn_kernel(
    const float* __restrict__ beta, float* __restrict__ out)
{
    extern __shared__ __align__(16) char smem[];
    __half* s_ql = (__half*)(smem + SM_QL);
    __half* s_qr = (__half*)(smem + SM_QR);
    __half* s_vt = (__half*)(smem + SM_VT);

    const int tid = threadIdx.x, wid = tid >> 5, lane = tid & 31;
    const int h = blockIdx.x, n = blockIdx.y;
    const size_t pbase = (size_t)(n * H_ + h) * W_ * 64;

    {
        const uint4* gql = (const uint4*)(g_Qlh + pbase);
        const uint4* gqr = (const uint4*)(g_Qrh + pbase);
        const uint4* gvt = (const uint4*)(g_Vth + pbase);
        for (int i = tid; i < 2048; i += 256) {
            int row = i >> 3, seg = i & 7;
            ((uint4*)(s_ql + row * QL_STRIDE))[seg] = gql[i];
            ((uint4*)(s_qr + row * QL_STRIDE))[seg] = gqr[i];
        }
        for (int i = tid; i < 2048; i += 256) {
            int row = i >> 5, seg = i & 31;
            ((uint4*)(s_vt + row * VT_STRIDE))[seg] = gvt[i];
        }
    }
    __syncthreads();

    const uint32_t ql_b = smem_u32(s_ql);
    const uint32_t qr_b = smem_u32(s_qr);
    const uint32_t vt_b = smem_u32(s_vt);
    const uint32_t p_b  = smem_u32(smem + SM_P) + wid * (16 * P_STRIDE * 2);

    const int r  = lane >> 2;
    const int tc = lane & 3;
    const int a_row = lane & 15, a_ch = lane >> 4;
    const int b_row = (lane & 7) + ((lane >> 4) << 3);
    const int b_ch  = (lane >> 3) & 1;
    const uint32_t p_addr = p_b + a_row * (P_STRIDE * 2) + a_ch * 16;

#pragma unroll 1
    for (int qt = 0; qt < 2; qt++) {
        const int qbase = (wid * 2 + qt) * 16;

        uint32_t aQ[4][4];
#pragma unroll
        for (int ks = 0; ks < 4; ks++) {
            uint32_t addr = ql_b + (qbase + a_row) * (QL_STRIDE * 2)
                          + (ks * 16 + a_ch * 8) * 2;
            ldsm_x4(aQ[ks], addr);
        }

        float o[8][4];
#pragma unroll
        for (int nc = 0; nc < 8; nc++)
#pragma unroll
            for (int j = 0; j < 4; j++) o[nc][j] = 0.f;
        float m_r = -1e30f, m_r8 = -1e30f;
        float l_r = 0.f,    l_r8 = 0.f;

#pragma unroll 1
        for (int kk = 0; kk < 16; kk++) {
            const int kbase = kk * 16;

            float s0[4] = {0.f, 0.f, 0.f, 0.f};
            float s1[4] = {0.f, 0.f, 0.f, 0.f};
#pragma unroll
            for (int ks = 0; ks < 4; ks++) {
                uint32_t br[4];
                uint32_t addr = qr_b + (kbase + b_row) * (QL_STRIDE * 2)
                              + (ks * 16 + b_ch * 8) * 2;
                ldsm_x4(br, addr);
                mma16816(s0, aQ[ks], br[0], br[1]);
                mma16816(s1, aQ[ks], br[2], br[3]);
            }

            float cm_r  = fmaxf(fmaxf(s0[0], s0[1]), fmaxf(s1[0], s1[1]));
            float cm_r8 = fmaxf(fmaxf(s0[2], s0[3]), fmaxf(s1[2], s1[3]));
            cm_r  = fmaxf(cm_r,  __shfl_xor_sync(0xffffffff, cm_r,  1));
            cm_r  = fmaxf(cm_r,  __shfl_xor_sync(0xffffffff, cm_r,  2));
            cm_r8 = fmaxf(cm_r8, __shfl_xor_sync(0xffffffff, cm_r8, 1));
            cm_r8 = fmaxf(cm_r8, __shfl_xor_sync(0xffffffff, cm_r8, 2));
            float mn_r  = fmaxf(m_r,  cm_r  * 0.125f);
            float mn_r8 = fmaxf(m_r8, cm_r8 * 0.125f);
            float al_r  = __expf(m_r  - mn_r);
            float al_r8 = __expf(m_r8 - mn_r8);
            m_r = mn_r; m_r8 = mn_r8;

            float p00 = __expf(fmaf(s0[0], 0.125f, -mn_r));
            float p01 = __expf(fmaf(s0[1], 0.125f, -mn_r));
            float p10 = __expf(fmaf(s1[0], 0.125f, -mn_r));
            float p11 = __expf(fmaf(s1[1], 0.125f, -mn_r));
            float q00 = __expf(fmaf(s0[2], 0.125f, -mn_r8));
            float q01 = __expf(fmaf(s0[3], 0.125f, -mn_r8));
            float q10 = __expf(fmaf(s1[2], 0.125f, -mn_r8));
            float q11 = __expf(fmaf(s1[3], 0.125f, -mn_r8));
            l_r  = l_r  * al_r  + (p00 + p01) + (p10 + p11);
            l_r8 = l_r8 * al_r8 + (q00 + q01) + (q10 + q11);

#pragma unroll
            for (int nc = 0; nc < 8; nc++) {
                o[nc][0] *= al_r;  o[nc][1] *= al_r;
                o[nc][2] *= al_r8; o[nc][3] *= al_r8;
            }

            __syncwarp();
            {
                __half* pw = (__half*)(smem + SM_P) + wid * (16 * P_STRIDE);
                *(__half2*)&pw[r * P_STRIDE + 2 * tc]           = __floats2half2_rn(p00, p01);
                *(__half2*)&pw[r * P_STRIDE + 8 + 2 * tc]       = __floats2half2_rn(p10, p11);
                *(__half2*)&pw[(r + 8) * P_STRIDE + 2 * tc]     = __floats2half2_rn(q00, q01);
                *(__half2*)&pw[(r + 8) * P_STRIDE + 8 + 2 * tc] = __floats2half2_rn(q10, q11);
            }
            __syncwarp();

            uint32_t aP[4];
            ldsm_x4(aP, p_addr);

#pragma unroll
            for (int vg = 0; vg < 4; vg++) {
                uint32_t bv[4];
                uint32_t addr = vt_b + (vg * 16 + b_row) * (VT_STRIDE * 2)
                              + (kbase + b_ch * 8) * 2;
                ldsm_x4(bv, addr);
                mma16816(o[2 * vg],     aP, bv[0], bv[1]);
                mma16816(o[2 * vg + 1], aP, bv[2], bv[3]);
            }
        }

        l_r  += __shfl_xor_sync(0xffffffff, l_r,  1);
        l_r  += __shfl_xor_sync(0xffffffff, l_r,  2);
        l_r8 += __shfl_xor_sync(0xffffffff, l_r8, 1);
        l_r8 += __shfl_xor_sync(0xffffffff, l_r8, 2);
        float inv_r  = __fdividef(1.f, l_r);
        float inv_r8 = __fdividef(1.f, l_r8);

#pragma unroll
        for (int nc = 0; nc < 8; nc++) {
            int c0 = nc * 8 + 2 * tc;
            float b0 = beta[c0], b1 = beta[c0 + 1];
            size_t base0 = (((size_t)n * 64 + c0) * H_ + h) * W_ + qbase;
            out[base0 + r]            += b0 * o[nc][0] * inv_r;
            out[base0 + HW_ + r]      += b1 * o[nc][1] * inv_r;
            out[base0 + r + 8]        += b0 * o[nc][2] * inv_r8;
            out[base0 + HW_ + r + 8]  += b1 * o[nc][3] * inv_r8;
        }
    }
}

// ---------------------------------------------------------------------------
extern "C" void kernel_launch(void* const* d_in, const int* in_sizes, int n_in,
                              void* d_out, int out_size)
{
    const float* x_l  = (const float*)d_in[0];
    const float* x_r  = (const float*)d_in[1];
    const float* nl_w = (const float*)d_in[2];
    const float* nl_b = (const float*)d_in[3];
    const float* nr_w = (const float*)d_in[4];
    const float* nr_b = (const float*)d_in[5];
    const float* Wq_l = (const float*)d_in[6];
    const float* bq_l = (const float*)d_in[7];
    const float* Wq_r = (const float*)d_in[8];
    const float* bq_r = (const float*)d_in[9];
    const float* Wv_r = (const float*)d_in[10];
    const float* bv_r = (const float*)d_in[11];
    const float* beta = (const float*)d_in[12];
    const float* gamma= (const float*)d_in[13];
    const float* W_hf = (const float*)d_in[14];
    const float* b_hf = (const float*)d_in[15];
    float* out = (float*)d_out;

    cudaFuncSetAttribute(proj_mma_kernel, cudaFuncAttributeMaxDynamicSharedMemorySize, PM_SMEM);
    cudaFuncSetAttribute(attn_kernel, cudaFuncAttributeMaxDynamicSharedMemorySize, AT_SMEM);
    cudaFuncSetAttribute(conv_mma_kernel, cudaFuncAttributeMaxDynamicSharedMemorySize, CV_SMEM);

    wconv_kernel<<<144, 256>>>(W_hf);
    pre_kernel  <<<dim3(W_/64, H_, N_), 256>>>(x_r);
    proj_mma_kernel<<<dim3(H_, N_), 256, PM_SMEM>>>(
        x_l, x_r, nl_w, nl_b, nr_w, nr_b, Wq_l, bq_l, Wq_r, bq_r, Wv_r, bv_r);
    conv_mma_kernel<<<dim3(W_/128, H_, N_), 256, CV_SMEM>>>(x_l, gamma, b_hf, out);
    attn_kernel <<<dim3(H_, N_), 256, AT_SMEM>>>(beta, out);
}

// round 13
// speedup vs baseline: 5.6431x; 1.1633x over previous
#include <cuda_runtime.h>
#include <cuda_fp16.h>
#include <math.h>
#include <stdint.h>

#define N_  8
#define C_  64
#define H_  128
#define W_  256
#define HW_ (H_*W_)            // 32768
#define NELEM (N_*C_*H_*W_)    // 16777216

// Scratch (device globals — no allocation in kernel_launch)
__device__ __half g_th [NELEM];   // hf input, pixel-major [n][h][w][c] fp16
__device__ __half g_W9h[9*64*64]; // conv weights, MMA-fragment order (see wconv)
__device__ __half g_Qlh[NELEM];   // [n,h,q,c]
__device__ __half g_Qrh[NELEM];   // [n,h,k,c]
__device__ __half g_Vth[NELEM];   // [n,h,c,k]

// ===========================================================================
__device__ __forceinline__ uint32_t smem_u32(const void* p) {
    uint32_t a;
    asm("{ .reg .u64 t; cvta.to.shared.u64 t, %1; cvt.u32.u64 %0, t; }"
        : "=r"(a) : "l"(p));
    return a;
}
__device__ __forceinline__ void ldsm_x4(uint32_t* r, uint32_t addr) {
    asm volatile("ldmatrix.sync.aligned.m8n8.x4.shared.b16 {%0,%1,%2,%3}, [%4];"
                 : "=r"(r[0]), "=r"(r[1]), "=r"(r[2]), "=r"(r[3]) : "r"(addr));
}
__device__ __forceinline__ void mma16816(float* d, const uint32_t* a,
                                         const uint32_t b0, const uint32_t b1) {
    asm volatile(
        "mma.sync.aligned.m16n8k16.row.col.f32.f16.f16.f32 "
        "{%0,%1,%2,%3}, {%4,%5,%6,%7}, {%8,%9}, {%0,%1,%2,%3};"
        : "+f"(d[0]), "+f"(d[1]), "+f"(d[2]), "+f"(d[3])
        : "r"(a[0]), "r"(a[1]), "r"(a[2]), "r"(a[3]), "r"(b0), "r"(b1));
}

// ---------------------------------------------------------------------------
// Kernel 0: W_hf (O,I,3,3) fp32 -> g_W9h in MMA A-fragment order:
// uint4 index (((tap*4+wm)*4+ks)*32 + lane) = that lane's 4 fragment words
// for the m16n8k16 A-tile (rows wm*16..+15, cols ks*16..+15).
// Fragment word j: row = wm*16 + (lane>>2) + (j&1)*8,
//                  col = ks*16 + 2*(lane&3) + (j>>1)*8   (2 halves)
// ---------------------------------------------------------------------------
__global__ void __launch_bounds__(256) wconv_kernel(const float* __restrict__ Whf)
{
    int i = blockIdx.x * 256 + threadIdx.x;          // uint32 index, 18432 total
    if (i < 9 * 4 * 4 * 32 * 4) {
        int j    = i & 3;
        int lane = (i >> 2) & 31;
        int ks   = (i >> 7) & 3;
        int wm   = (i >> 9) & 3;
        int tap  = i >> 11;
        int row = wm * 16 + (lane >> 2) + (j & 1) * 8;
        int col = ks * 16 + 2 * (lane & 3) + (j >> 1) * 8;
        float w0 = Whf[(row * 64 + col) * 9 + tap];
        float w1 = Whf[(row * 64 + col + 1) * 9 + tap];
        ((__half2*)g_W9h)[i] = __floats2half2_rn(w0, w1);
    }
}

// ---------------------------------------------------------------------------
// Kernel 1: t = x_r - avgpool3x3(x_r), fp16 pixel-major out
// ---------------------------------------------------------------------------
#define PB_STRIDE 72
__global__ void __launch_bounds__(256) pre_kernel(const float* __restrict__ xr)
{
    __shared__ __half s_buf[64 * PB_STRIDE];

    const int tid = threadIdx.x;
    const int w0 = blockIdx.x * 64, h = blockIdx.y, n = blockIdx.z;
    const int cg = tid >> 6, w = tid & 63;
    const int gw = w0 + w;

#pragma unroll 1
    for (int c0 = 0; c0 < 64; c0 += 4) {
        int c = c0 + cg;
        const float* p = xr + (size_t)(n * 64 + c) * HW_;
        float s = 0.f;
#pragma unroll
        for (int dy = -1; dy <= 1; dy++) {
            int hh = h + dy;
            if ((unsigned)hh < (unsigned)H_) {
#pragma unroll
                for (int dx = -1; dx <= 1; dx++) {
                    int ww = gw + dx;
                    if ((unsigned)ww < (unsigned)W_) s += p[hh * W_ + ww];
                }
            }
        }
        s_buf[w * PB_STRIDE + c] = __float2half(p[h * W_ + gw] - s * (1.0f / 9.0f));
    }
    __syncthreads();

    uint4* dst = (uint4*)(g_th + ((size_t)(n * H_ + h) * W_ + w0) * 64);
    for (int i = tid; i < 512; i += 256) {
        int px = i >> 3, seg = i & 7;
        dst[px * 8 + seg] = *(uint4*)&s_buf[px * PB_STRIDE + seg * 8];
    }
}

// ---------------------------------------------------------------------------
// Kernel 2: out = x_l + gamma * (conv3x3(t) + b_hf) — HMMA implicit GEMM
// grid (W/128, H, N). smem: swizzled t-tile only (48.75KB) -> 4 CTA/SM.
// Weights: ONE coalesced LDG.128 per (tap,ks) from fragment-ordered g_W9h.
// ---------------------------------------------------------------------------
#define CV_SMEM (3 * 130 * 128)                   // 49920 bytes

__global__ void __launch_bounds__(256, 4) conv_mma_kernel(
    const float* __restrict__ xl, const float* __restrict__ gamma,
    const float* __restrict__ bhf, float* __restrict__ out)
{
    extern __shared__ __align__(16) char smem[];

    const int tid = threadIdx.x, wid = tid >> 5, lane = tid & 31;
    const int w0 = blockIdx.x * 128, h = blockIdx.y, n = blockIdx.z;

    // ---- load t tile (3 h-rows x 130 px x 128B), XOR-swizzled, zero OOB ----
    for (int i = tid; i < 3120; i += 256) {
        int hr = i / 1040, rem = i - hr * 1040;
        int px = rem >> 3, seg = rem & 7;
        int row = hr * 130 + px;
        int gh = h - 1 + hr, gw = w0 - 1 + px;
        uint4 v = make_uint4(0, 0, 0, 0);
        if ((unsigned)gh < (unsigned)H_ && (unsigned)gw < (unsigned)W_)
            v = *(const uint4*)(g_th + ((size_t)(n * H_ + gh) * W_ + gw) * 64 + seg * 8);
        *(uint4*)(smem + row * 128 + ((seg ^ (row & 7)) << 4)) = v;
    }
    __syncthreads();

    const int wm = wid >> 1, wn = wid & 1;
    const int r = lane >> 2, tc = lane & 3;
    const int b_row = (lane & 7) + ((lane >> 4) << 3);
    const int b_ch  = (lane >> 3) & 1;
    const uint32_t st_b = smem_u32(smem);

    float acc[8][4];
#pragma unroll
    for (int nt = 0; nt < 8; nt++)
#pragma unroll
        for (int j = 0; j < 4; j++) acc[nt][j] = 0.f;

    const uint4* wfrag = (const uint4*)g_W9h;

#pragma unroll 1
    for (int tap = 0; tap < 9; tap++) {
        const int ty = tap / 3, tx = tap - ty * 3;

        // A-fragments: one coalesced 16B load per ks
        uint32_t aW[4][4];
#pragma unroll
        for (int ks = 0; ks < 4; ks++) {
            uint4 t = wfrag[((tap * 4 + wm) * 4 + ks) * 32 + lane];
            aW[ks][0] = t.x; aW[ks][1] = t.y; aW[ks][2] = t.z; aW[ks][3] = t.w;
        }

#pragma unroll
        for (int ks = 0; ks < 4; ks++) {
#pragma unroll
            for (int np = 0; np < 4; np++) {
                int row_t = ty * 130 + wn * 64 + tx + np * 16 + b_row;
                int chunk = ks * 2 + b_ch;
                uint32_t addr = st_b + row_t * 128 + ((chunk ^ (row_t & 7)) << 4);
                uint32_t bv[4];
                ldsm_x4(bv, addr);
                mma16816(acc[2 * np],     aW[ks], bv[0], bv[1]);
                mma16816(acc[2 * np + 1], aW[ks], bv[2], bv[3]);
            }
        }
    }

    // ---- epilogue ----
    const int o0 = wm * 16 + r, o1 = o0 + 8;
    const float g0 = gamma[o0], bb0 = bhf[o0];
    const float g1 = gamma[o1], bb1 = bhf[o1];
    const size_t row0 = ((size_t)(n * 64 + o0) * H_ + h) * W_;
    const size_t row1 = ((size_t)(n * 64 + o1) * H_ + h) * W_;
#pragma unroll
    for (int nt = 0; nt < 8; nt++) {
        int p = w0 + wn * 64 + nt * 8 + 2 * tc;
        out[row0 + p]     = xl[row0 + p]     + g0 * (acc[nt][0] + bb0);
        out[row0 + p + 1] = xl[row0 + p + 1] + g0 * (acc[nt][1] + bb0);
        out[row1 + p]     = xl[row1 + p]     + g1 * (acc[nt][2] + bb1);
        out[row1 + p + 1] = xl[row1 + p + 1] + g1 * (acc[nt][3] + bb1);
    }
}

// ---------------------------------------------------------------------------
// Kernel 3: fused LayerNorm + 1x1 projections — HMMA version
// ---------------------------------------------------------------------------
#define PM_NL   0
#define PM_NR   (PM_NL + 256 * 72 * 2)      // 36864
#define PM_RAW  (PM_NR + 256 * 72 * 2)      // 73728
#define PM_W    (PM_RAW + 256 * 72 * 2)     // 110592  [3][64][72]
#define PM_CW   (PM_W + 3 * 64 * 72 * 2)    // 138240
#define PM_B    (PM_CW + 4 * 64 * 4)        // 139264
#define PM_SMEM (PM_B + 3 * 64 * 4)         // 140032

__global__ void __launch_bounds__(256) proj_mma_kernel(
    const float* __restrict__ xl, const float* __restrict__ xr,
    const float* __restrict__ nlw, const float* __restrict__ nlb,
    const float* __restrict__ nrw, const float* __restrict__ nrb,
    const float* __restrict__ Wql, const float* __restrict__ bql,
    const float* __restrict__ Wqr, const float* __restrict__ bqr,
    const float* __restrict__ Wvr, const float* __restrict__ bvr)
{
    extern __shared__ __align__(16) char smem[];
    __half* s_nl  = (__half*)(smem + PM_NL);
    __half* s_nr  = (__half*)(smem + PM_NR);
    __half* s_raw = (__half*)(smem + PM_RAW);
    __half* s_w   = (__half*)(smem + PM_W);
    float*  s_cw  = (float*)(smem + PM_CW);
    float*  s_b   = (float*)(smem + PM_B);

    const int tid = threadIdx.x, wid = tid >> 5, lane = tid & 31;
    const int h = blockIdx.x, n = blockIdx.y;
    const size_t base0 = (size_t)(n * 64 * H_ + h) * W_ + tid;
    const size_t pbase = (size_t)(n * H_ + h) * W_ * 64;

    if (tid < 64) {
        s_cw[tid]       = nlw[tid];
        s_cw[64 + tid]  = nlb[tid];
        s_cw[128 + tid] = nrw[tid];
        s_cw[192 + tid] = nrb[tid];
        s_b[tid]        = bql[tid];
        s_b[64 + tid]   = bqr[tid];
        s_b[128 + tid]  = bvr[tid];
    }

    {
        float v[64];
        float s = 0.f, sq = 0.f;
#pragma unroll
        for (int c = 0; c < 64; c++) {
            v[c] = xr[base0 + (size_t)c * HW_];
            s += v[c]; sq += v[c] * v[c];
        }
        float mu = s * (1.0f / 64.0f);
        float rs = rsqrtf(sq * (1.0f / 64.0f) - mu * mu + 1e-6f);
        __syncthreads();
#pragma unroll
        for (int c = 0; c < 64; c += 2) {
            *(__half2*)&s_raw[tid * 72 + c] = __floats2half2_rn(v[c], v[c + 1]);
            float n0 = (v[c]     - mu) * rs * s_cw[128 + c]     + s_cw[192 + c];
            float n1 = (v[c + 1] - mu) * rs * s_cw[128 + c + 1] + s_cw[192 + c + 1];
            *(__half2*)&s_nr[tid * 72 + c] = __floats2half2_rn(n0, n1);
        }
    }
    {
        float v[64];
        float s = 0.f, sq = 0.f;
#pragma unroll
        for (int c = 0; c < 64; c++) {
            v[c] = xl[base0 + (size_t)c * HW_];
            s += v[c]; sq += v[c] * v[c];
        }
        float mu = s * (1.0f / 64.0f);
        float rs = rsqrtf(sq * (1.0f / 64.0f) - mu * mu + 1e-6f);
#pragma unroll
        for (int c = 0; c < 64; c += 2) {
            float n0 = (v[c]     - mu) * rs * s_cw[c]     + s_cw[64 + c];
            float n1 = (v[c + 1] - mu) * rs * s_cw[c + 1] + s_cw[64 + c + 1];
            *(__half2*)&s_nl[tid * 72 + c] = __floats2half2_rn(n0, n1);
        }
    }
    for (int i = tid; i < 4096; i += 256) {
        int o = i >> 6, c = i & 63;
        s_w[o * 72 + c]         = __float2half(Wql[i]);
        s_w[(64 + o) * 72 + c]  = __float2half(Wqr[i]);
        s_w[(128 + o) * 72 + c] = __float2half(Wvr[i]);
    }
    __syncthreads();

    const int a_row = lane & 15, a_ch = lane >> 4;
    const int b_row = (lane & 7) + ((lane >> 4) << 3);
    const int b_ch  = (lane >> 3) & 1;
    const int r = lane >> 2, tc = lane & 3;
    const uint32_t w_b = smem_u32(s_w);

#pragma unroll 1
    for (int g = 0; g < 2; g++) {
        const uint32_t x_b = smem_u32(g ? s_nr : s_nl);
        __half* gq = (g ? g_Qrh : g_Qlh) + pbase;
#pragma unroll 1
        for (int mt = 0; mt < 2; mt++) {
            const int px0 = wid * 32 + mt * 16;
            uint32_t aA[4][4];
#pragma unroll
            for (int ks = 0; ks < 4; ks++)
                ldsm_x4(aA[ks], x_b + ((px0 + a_row) * 72 + ks * 16 + a_ch * 8) * 2);

            float acc[8][4];
#pragma unroll
            for (int nt = 0; nt < 8; nt++)
#pragma unroll
                for (int j = 0; j < 4; j++) acc[nt][j] = 0.f;

#pragma unroll
            for (int nt4 = 0; nt4 < 4; nt4++) {
                const uint32_t wb = w_b + ((g * 64 + nt4 * 16 + b_row) * 72
                                           + b_ch * 8) * 2;
#pragma unroll
                for (int ks = 0; ks < 4; ks++) {
                    uint32_t bw[4];
                    ldsm_x4(bw, wb + ks * 32);
                    mma16816(acc[2 * nt4],     aA[ks], bw[0], bw[1]);
                    mma16816(acc[2 * nt4 + 1], aA[ks], bw[2], bw[3]);
                }
            }
#pragma unroll
            for (int nc = 0; nc < 8; nc++) {
                int o = nc * 8 + 2 * tc;
                float b0 = s_b[g * 64 + o], b1 = s_b[g * 64 + o + 1];
                *(__half2*)&gq[(size_t)(px0 + r) * 64 + o] =
                    __floats2half2_rn(acc[nc][0] + b0, acc[nc][1] + b1);
                *(__half2*)&gq[(size_t)(px0 + r + 8) * 64 + o] =
                    __floats2half2_rn(acc[nc][2] + b0, acc[nc][3] + b1);
            }
        }
    }

    {
        const int mt = wid >> 1, nh = wid & 1;
        const uint32_t raw_b = smem_u32(s_raw);
        uint32_t aA[4][4];
#pragma unroll
        for (int ks = 0; ks < 4; ks++)
            ldsm_x4(aA[ks], w_b + ((128 + mt * 16 + a_row) * 72 + ks * 16
                                   + a_ch * 8) * 2);

        float acc[16][4];
#pragma unroll
        for (int j = 0; j < 16; j++)
#pragma unroll
            for (int k = 0; k < 4; k++) acc[j][k] = 0.f;

#pragma unroll
        for (int nt = 0; nt < 8; nt++) {
            const uint32_t bb = raw_b + ((nh * 128 + nt * 16 + b_row) * 72
                                         + b_ch * 8) * 2;
#pragma unroll
            for (int ks = 0; ks < 4; ks++) {
                uint32_t bv[4];
                ldsm_x4(bv, bb + ks * 32);
                mma16816(acc[2 * nt],     aA[ks], bv[0], bv[1]);
                mma16816(acc[2 * nt + 1], aA[ks], bv[2], bv[3]);
            }
        }

        const int o0 = mt * 16 + r, o1 = o0 + 8;
        const float b0 = s_b[128 + o0], b1 = s_b[128 + o1];
        __half* gvt = g_Vth + pbase;
#pragma unroll
        for (int j = 0; j < 16; j++) {
            int px = nh * 128 + j * 8 + 2 * tc;
            *(__half2*)&gvt[(size_t)o0 * 256 + px] =
                __floats2half2_rn(acc[j][0] + b0, acc[j][1] + b0);
            *(__half2*)&gvt[(size_t)o1 * 256 + px] =
                __floats2half2_rn(acc[j][2] + b1, acc[j][3] + b1);
        }
    }
}

// ---------------------------------------------------------------------------
// Kernel 4: warp-MMA fp16 cross attention (mma.sync m16n8k16).
// ---------------------------------------------------------------------------
#define QL_STRIDE 72      // halves
#define VT_STRIDE 264     // halves
#define P_STRIDE  24      // halves
#define SM_QL 0
#define SM_QR (SM_QL + 256 * QL_STRIDE * 2)          // 36864
#define SM_VT (SM_QR + 256 * QL_STRIDE * 2)          // 73728
#define SM_P  (SM_VT + 64 * VT_STRIDE * 2)           // 107520
#define AT_SMEM (SM_P + 8 * 16 * P_STRIDE * 2)       // 113664

__global__ void __launch_bounds__(256, 2) attn_kernel(
    const float* __restrict__ beta, float* __restrict__ out)
{
    extern __shared__ __align__(16) char smem[];
    __half* s_ql = (__half*)(smem + SM_QL);
    __half* s_qr = (__half*)(smem + SM_QR);
    __half* s_vt = (__half*)(smem + SM_VT);

    const int tid = threadIdx.x, wid = tid >> 5, lane = tid & 31;
    const int h = blockIdx.x, n = blockIdx.y;
    const size_t pbase = (size_t)(n * H_ + h) * W_ * 64;

    {
        const uint4* gql = (const uint4*)(g_Qlh + pbase);
        const uint4* gqr = (const uint4*)(g_Qrh + pbase);
        const uint4* gvt = (const uint4*)(g_Vth + pbase);
        for (int i = tid; i < 2048; i += 256) {
            int row = i >> 3, seg = i & 7;
            ((uint4*)(s_ql + row * QL_STRIDE))[seg] = gql[i];
            ((uint4*)(s_qr + row * QL_STRIDE))[seg] = gqr[i];
        }
        for (int i = tid; i < 2048; i += 256) {
            int row = i >> 5, seg = i & 31;
            ((uint4*)(s_vt + row * VT_STRIDE))[seg] = gvt[i];
        }
    }
    __syncthreads();

    const uint32_t ql_b = smem_u32(s_ql);
    const uint32_t qr_b = smem_u32(s_qr);
    const uint32_t vt_b = smem_u32(s_vt);
    const uint32_t p_b  = smem_u32(smem + SM_P) + wid * (16 * P_STRIDE * 2);

    const int r  = lane >> 2;
    const int tc = lane & 3;
    const int a_row = lane & 15, a_ch = lane >> 4;
    const int b_row = (lane & 7) + ((lane >> 4) << 3);
    const int b_ch  = (lane >> 3) & 1;
    const uint32_t p_addr = p_b + a_row * (P_STRIDE * 2) + a_ch * 16;

#pragma unroll 1
    for (int qt = 0; qt < 2; qt++) {
        const int qbase = (wid * 2 + qt) * 16;

        uint32_t aQ[4][4];
#pragma unroll
        for (int ks = 0; ks < 4; ks++) {
            uint32_t addr = ql_b + (qbase + a_row) * (QL_STRIDE * 2)
                          + (ks * 16 + a_ch * 8) * 2;
            ldsm_x4(aQ[ks], addr);
        }

        float o[8][4];
#pragma unroll
        for (int nc = 0; nc < 8; nc++)
#pragma unroll
            for (int j = 0; j < 4; j++) o[nc][j] = 0.f;
        float m_r = -1e30f, m_r8 = -1e30f;
        float l_r = 0.f,    l_r8 = 0.f;

#pragma unroll 1
        for (int kk = 0; kk < 16; kk++) {
            const int kbase = kk * 16;

            float s0[4] = {0.f, 0.f, 0.f, 0.f};
            float s1[4] = {0.f, 0.f, 0.f, 0.f};
#pragma unroll
            for (int ks = 0; ks < 4; ks++) {
                uint32_t br[4];
                uint32_t addr = qr_b + (kbase + b_row) * (QL_STRIDE * 2)
                              + (ks * 16 + b_ch * 8) * 2;
                ldsm_x4(br, addr);
                mma16816(s0, aQ[ks], br[0], br[1]);
                mma16816(s1, aQ[ks], br[2], br[3]);
            }

            float cm_r  = fmaxf(fmaxf(s0[0], s0[1]), fmaxf(s1[0], s1[1]));
            float cm_r8 = fmaxf(fmaxf(s0[2], s0[3]), fmaxf(s1[2], s1[3]));
            cm_r  = fmaxf(cm_r,  __shfl_xor_sync(0xffffffff, cm_r,  1));
            cm_r  = fmaxf(cm_r,  __shfl_xor_sync(0xffffffff, cm_r,  2));
            cm_r8 = fmaxf(cm_r8, __shfl_xor_sync(0xffffffff, cm_r8, 1));
            cm_r8 = fmaxf(cm_r8, __shfl_xor_sync(0xffffffff, cm_r8, 2));
            float mn_r  = fmaxf(m_r,  cm_r  * 0.125f);
            float mn_r8 = fmaxf(m_r8, cm_r8 * 0.125f);
            float al_r  = __expf(m_r  - mn_r);
            float al_r8 = __expf(m_r8 - mn_r8);
            m_r = mn_r; m_r8 = mn_r8;

            float p00 = __expf(fmaf(s0[0], 0.125f, -mn_r));
            float p01 = __expf(fmaf(s0[1], 0.125f, -mn_r));
            float p10 = __expf(fmaf(s1[0], 0.125f, -mn_r));
            float p11 = __expf(fmaf(s1[1], 0.125f, -mn_r));
            float q00 = __expf(fmaf(s0[2], 0.125f, -mn_r8));
            float q01 = __expf(fmaf(s0[3], 0.125f, -mn_r8));
            float q10 = __expf(fmaf(s1[2], 0.125f, -mn_r8));
            float q11 = __expf(fmaf(s1[3], 0.125f, -mn_r8));
            l_r  = l_r  * al_r  + (p00 + p01) + (p10 + p11);
            l_r8 = l_r8 * al_r8 + (q00 + q01) + (q10 + q11);

#pragma unroll
            for (int nc = 0; nc < 8; nc++) {
                o[nc][0] *= al_r;  o[nc][1] *= al_r;
                o[nc][2] *= al_r8; o[nc][3] *= al_r8;
            }

            __syncwarp();
            {
                __half* pw = (__half*)(smem + SM_P) + wid * (16 * P_STRIDE);
                *(__half2*)&pw[r * P_STRIDE + 2 * tc]           = __floats2half2_rn(p00, p01);
                *(__half2*)&pw[r * P_STRIDE + 8 + 2 * tc]       = __floats2half2_rn(p10, p11);
                *(__half2*)&pw[(r + 8) * P_STRIDE + 2 * tc]     = __floats2half2_rn(q00, q01);
                *(__half2*)&pw[(r + 8) * P_STRIDE + 8 + 2 * tc] = __floats2half2_rn(q10, q11);
            }
            __syncwarp();

            uint32_t aP[4];
            ldsm_x4(aP, p_addr);

#pragma unroll
            for (int vg = 0; vg < 4; vg++) {
                uint32_t bv[4];
                uint32_t addr = vt_b + (vg * 16 + b_row) * (VT_STRIDE * 2)
                              + (kbase + b_ch * 8) * 2;
                ldsm_x4(bv, addr);
                mma16816(o[2 * vg],     aP, bv[0], bv[1]);
                mma16816(o[2 * vg + 1], aP, bv[2], bv[3]);
            }
        }

        l_r  += __shfl_xor_sync(0xffffffff, l_r,  1);
        l_r  += __shfl_xor_sync(0xffffffff, l_r,  2);
        l_r8 += __shfl_xor_sync(0xffffffff, l_r8, 1);
        l_r8 += __shfl_xor_sync(0xffffffff, l_r8, 2);
        float inv_r  = __fdividef(1.f, l_r);
        float inv_r8 = __fdividef(1.f, l_r8);

#pragma unroll
        for (int nc = 0; nc < 8; nc++) {
            int c0 = nc * 8 + 2 * tc;
            float b0 = beta[c0], b1 = beta[c0 + 1];
            size_t base0 = (((size_t)n * 64 + c0) * H_ + h) * W_ + qbase;
            out[base0 + r]            += b0 * o[nc][0] * inv_r;
            out[base0 + HW_ + r]      += b1 * o[nc][1] * inv_r;
            out[base0 + r + 8]        += b0 * o[nc][2] * inv_r8;
            out[base0 + HW_ + r + 8]  += b1 * o[nc][3] * inv_r8;
        }
    }
}

// ---------------------------------------------------------------------------
extern "C" void kernel_launch(void* const* d_in, const int* in_sizes, int n_in,
                              void* d_out, int out_size)
{
    const float* x_l  = (const float*)d_in[0];
    const float* x_r  = (const float*)d_in[1];
    const float* nl_w = (const float*)d_in[2];
    const float* nl_b = (const float*)d_in[3];
    const float* nr_w = (const float*)d_in[4];
    const float* nr_b = (const float*)d_in[5];
    const float* Wq_l = (const float*)d_in[6];
    const float* bq_l = (const float*)d_in[7];
    const float* Wq_r = (const float*)d_in[8];
    const float* bq_r = (const float*)d_in[9];
    const float* Wv_r = (const float*)d_in[10];
    const float* bv_r = (const float*)d_in[11];
    const float* beta = (const float*)d_in[12];
    const float* gamma= (const float*)d_in[13];
    const float* W_hf = (const float*)d_in[14];
    const float* b_hf = (const float*)d_in[15];
    float* out = (float*)d_out;

    cudaFuncSetAttribute(proj_mma_kernel, cudaFuncAttributeMaxDynamicSharedMemorySize, PM_SMEM);
    cudaFuncSetAttribute(attn_kernel, cudaFuncAttributeMaxDynamicSharedMemorySize, AT_SMEM);
    cudaFuncSetAttribute(conv_mma_kernel, cudaFuncAttributeMaxDynamicSharedMemorySize, CV_SMEM);

    wconv_kernel<<<72, 256>>>(W_hf);
    pre_kernel  <<<dim3(W_/64, H_, N_), 256>>>(x_r);
    proj_mma_kernel<<<dim3(H_, N_), 256, PM_SMEM>>>(
        x_l, x_r, nl_w, nl_b, nr_w, nr_b, Wq_l, bq_l, Wq_r, bq_r, Wv_r, bv_r);
    conv_mma_kernel<<<dim3(W_/128, H_, N_), 256, CV_SMEM>>>(x_l, gamma, b_hf, out);
    attn_kernel <<<dim3(H_, N_), 256, AT_SMEM>>>(beta, out);
}